// round 14
// baseline (speedup 1.0000x reference)
#include <cuda_runtime.h>
#include <cuda_fp16.h>
#include <cstdint>
#include <cstddef>

// ---------------------------------------------------------------------------
// AttentionalPropagation, B=2, D=256, H=4, dim=64, N=M=4096.
// R14: R11 base + split-K flash (2 key-halves, exact via no-max softmax),
//      3 CTAs/SM residency, fp32 partial O/l + combine kernel.
// ---------------------------------------------------------------------------

#define BB 2
#define DD 256
#define HH 4

__device__ __half g_q[BB * HH * 4096 * 64];   // [b][h][n][di], pre-scaled
__device__ __half g_k[BB * HH * 4096 * 64];   // [b][h][m][di]
__device__ __half g_v[BB * HH * 64 * 4096];   // [b][h][di][m] (transposed)
__device__ __half g_xt  [BB * 4096 * DD];     // x  transposed (B,N,256) fp16
__device__ __half g_st  [BB * 4096 * DD];     // src transposed
__device__ __half g_attn[BB * 4096 * DD];     // attn (B,N,256), ch = h*64+di
__device__ __half g_h   [BB * 2 * DD * 4096]; // (B,2D,N) fp16 (pre-norm)
__device__ __half g_ht  [BB * 4096 * 2 * DD]; // (B,N,512) fp16 (post-norm)
__device__ __half g_wts [655360];             // fp16 weights
__device__ __half g_wcat[512 * 512];          // [W1x | perm(W1m@Wm)] fp16
__device__ float  g_bf  [512];                // W1m@bm + b1
__device__ float  g_stats[BB * 2 * DD * 2];   // per (b,c): mean, inv
__device__ float  g_opart[2 * BB * HH * 4096 * 64];  // partial O per split
__device__ float  g_lpart[2 * BB * HH * 4096];       // partial l per split

#define OFF_WQ 0
#define OFF_WK 65536
#define OFF_WV 131072
#define OFF_WM 196608
#define OFF_W1 262144
#define OFF_W2 524288

#define QSCALE (0.125f * 1.44269504088896340736f)

// ============================ PTX helpers ==================================
__device__ __forceinline__ uint32_t smem_u32(const void* p) {
    uint32_t a;
    asm("{ .reg .u64 t; cvta.to.shared.u64 t, %1; cvt.u32.u64 %0, t; }"
        : "=r"(a) : "l"(p));
    return a;
}
__device__ __forceinline__ uint32_t packh(float lo, float hi) {
    __half2 h = __floats2half2_rn(lo, hi);
    return *reinterpret_cast<uint32_t*>(&h);
}
__device__ __forceinline__ uint32_t ex2h2(uint32_t h2) {
    uint32_t r; asm("ex2.approx.f16x2 %0, %1;" : "=r"(r) : "r"(h2)); return r;
}
__device__ __forceinline__ void mma16f(float* d, const uint32_t* a,
                                       uint32_t b0, uint32_t b1) {
    asm volatile("mma.sync.aligned.m16n8k16.row.col.f32.f16.f16.f32 "
        "{%0,%1,%2,%3}, {%4,%5,%6,%7}, {%8,%9}, {%0,%1,%2,%3};"
        : "+f"(d[0]), "+f"(d[1]), "+f"(d[2]), "+f"(d[3])
        : "r"(a[0]), "r"(a[1]), "r"(a[2]), "r"(a[3]), "r"(b0), "r"(b1));
}
__device__ __forceinline__ void ldsm4(uint32_t* r, uint32_t addr) {
    asm volatile("ldmatrix.sync.aligned.m8n8.x4.shared.b16 {%0,%1,%2,%3}, [%4];"
        : "=r"(r[0]), "=r"(r[1]), "=r"(r[2]), "=r"(r[3]) : "r"(addr));
}
__device__ __forceinline__ void cp16(uint32_t s, const void* g) {
    asm volatile("cp.async.ca.shared.global [%0], [%1], 16;" :: "r"(s), "l"(g));
}
#define CP_COMMIT() asm volatile("cp.async.commit_group;" ::: "memory")
#define CP_WAIT(n)  asm volatile("cp.async.wait_group %0;" :: "n"(n) : "memory")

// ---------------------------------------------------------------------------
// producers
// ---------------------------------------------------------------------------
__global__ void round_weights(const float* __restrict__ wq, const float* __restrict__ wk,
                              const float* __restrict__ wv, const float* __restrict__ wm,
                              const float* __restrict__ w1, const float* __restrict__ w2,
                              __half* __restrict__ dst)
{
    int i = blockIdx.x * 256 + threadIdx.x;
    if (i >= 655360) return;
    float v;
    if      (i < OFF_WK) v = wq[i - OFF_WQ];
    else if (i < OFF_WV) v = wk[i - OFF_WK];
    else if (i < OFF_WM) v = wv[i - OFF_WV];
    else if (i < OFF_W1) v = wm[i - OFF_WM];
    else if (i < OFF_W2) v = w1[i - OFF_W1];
    else                 v = w2[i - OFF_W2];
    dst[i] = __float2half_rn(v);
}

__global__ void transpose_in(const float* __restrict__ x, const float* __restrict__ src,
                             __half* __restrict__ xt, __half* __restrict__ st, int N)
{
    __shared__ __half tile[32][33];
    const int which = blockIdx.z >> 1, b = blockIdx.z & 1;
    const float* in = which ? src : x;
    __half* out = which ? st : xt;
    const int c0 = blockIdx.y * 32, n0 = blockIdx.x * 32;
    const int tx = threadIdx.x & 31, ty = threadIdx.x >> 5;

    #pragma unroll
    for (int i = 0; i < 4; i++) {
        int c = ty + i * 8;
        tile[c][tx] = __float2half_rn(in[((size_t)(b * DD + c0 + c)) * N + n0 + tx]);
    }
    __syncthreads();
    #pragma unroll
    for (int i = 0; i < 4; i++) {
        int n = ty + i * 8;
        out[((size_t)b * N + n0 + n) * DD + c0 + tx] = tile[tx][n];
    }
}

__global__ void fuse_w1(const __half* __restrict__ wts, const float* __restrict__ b1,
                        const float* __restrict__ bm,
                        __half* __restrict__ wcat, float* __restrict__ bf)
{
    const __half* w1 = wts + OFF_W1;
    const __half* wm = wts + OFF_WM;
    int o = blockIdx.x, j = threadIdx.x;

    wcat[o * 512 + j] = w1[o * 512 + j];

    float acc = 0.f;
    const __half* w1m = w1 + o * 512 + 256;
    #pragma unroll 8
    for (int kk = 0; kk < 256; kk++)
        acc = fmaf(__half2float(w1m[kk]), __half2float(wm[kk * 256 + j]), acc);
    int jp = (j & 3) * 64 + (j >> 2);
    wcat[o * 512 + 256 + jp] = __float2half_rn(acc);

    if (j == 0) {
        float b = b1[o];
        for (int kk = 0; kk < 256; kk++)
            b = fmaf(__half2float(w1m[kk]), __half2float(bm[kk]), b);
        bf[o] = b;
    }
}

// ---------------------------------------------------------------------------
// fp16 flash attention, split-K over 2 key halves (exact: no-max softmax =>
// partial O/l combine by addition). grid (N/128, H, B*2); z = split*B + b.
// 4 warps x 32 q-rows; R11 inner loop; 3 CTAs/SM via launch_bounds(128,3).
// Writes fp32 partial O (undivided) + l to scratch.
// ---------------------------------------------------------------------------
#define LDB   72
#define VROWS 72

__global__ void __launch_bounds__(128, 3)
flash_attn_fp16(const __half* __restrict__ q, const __half* __restrict__ k,
                const __half* __restrict__ v, float* __restrict__ opart,
                float* __restrict__ lpart, int N, int M)
{
    extern __shared__ char smb[];
    __half* Ks = reinterpret_cast<__half*>(smb);             // [2][64][LDB]
    __half* Vs = reinterpret_cast<__half*>(smb + 18432);     // [2][VROWS][LDB]
    __half* Qs = reinterpret_cast<__half*>(smb + 39168);     // [128][LDB]
    float*  OT = reinterpret_cast<float*>(smb);              // [128][68] epilogue

    const int b  = blockIdx.z & 1, split = blockIdx.z >> 1;
    const int h  = blockIdx.y;
    const int n0 = blockIdx.x * 128;
    const int bh = b * HH + h;
    const int t  = threadIdx.x;
    const int wid = t >> 5, lane = t & 31;
    const int g = lane >> 2, tg = lane & 3;
    const int wr = wid * 32;
    const int lrow = lane & 7;
    const int lcol = (lane >> 3) * 8;

    const int Mh = M / 2;
    const __half* Kg = k + (size_t)bh * M * 64 + (size_t)split * Mh * 64;
    const __half* Vg = v + (size_t)bh * 64 * M + (size_t)split * Mh;

    // prefetch K/V tile 0
    {
        uint32_t kd = smem_u32(Ks), vd = smem_u32(Vs);
        #pragma unroll
        for (int i = 0; i < 4; i++) {
            int idx = t + i * 128;
            int r = idx >> 3, c = (idx & 7) * 8;
            cp16(kd + (uint32_t)(r * LDB + c) * 2, Kg + r * 64 + c);
            cp16(vd + (uint32_t)(r * LDB + c) * 2, Vg + (size_t)r * M + c);
        }
        CP_COMMIT();
    }

    // ones/zeros rows 64..71 of both V buffers
    {
        const __half one = __float2half(1.0f);
        const __half zer = __float2half(0.0f);
        for (int i = t; i < 2 * 8 * LDB; i += 128) {
            int buf = i / (8 * LDB);
            int rem = i - buf * 8 * LDB;
            int r = rem / LDB, c = rem - r * LDB;
            Vs[(size_t)buf * VROWS * LDB + (64 + r) * LDB + c] = (r == 0) ? one : zer;
        }
    }

    // stage Q
    {
        const __half* Qg = q + ((size_t)bh * N + n0) * 64;
        #pragma unroll
        for (int i = 0; i < 8; i++) {
            int idx = t + i * 128;
            int r = idx >> 3, c = (idx & 7) * 8;
            *reinterpret_cast<uint4*>(Qs + r * LDB + c) =
                *reinterpret_cast<const uint4*>(Qg + r * 64 + c);
        }
    }
    __syncthreads();

    // persistent Q fragments
    uint32_t Qf[2][4][4];
    #pragma unroll
    for (int mt = 0; mt < 2; mt++) {
        int r0 = wr + mt * 16 + g;
        #pragma unroll
        for (int kk = 0; kk < 4; kk++) {
            Qf[mt][kk][0] = *reinterpret_cast<uint32_t*>(Qs + (r0    ) * LDB + kk * 16 + 2 * tg);
            Qf[mt][kk][1] = *reinterpret_cast<uint32_t*>(Qs + (r0 + 8) * LDB + kk * 16 + 2 * tg);
            Qf[mt][kk][2] = *reinterpret_cast<uint32_t*>(Qs + (r0    ) * LDB + kk * 16 + 2 * tg + 8);
            Qf[mt][kk][3] = *reinterpret_cast<uint32_t*>(Qs + (r0 + 8) * LDB + kk * 16 + 2 * tg + 8);
        }
    }
    __syncthreads();

    float Of[9][2][4] = {};     // Of[8] = l accumulators via ones column

    const int nT = Mh / 64;
    for (int tt = 0; tt < nT; tt++) {
        const __half* Kc = Ks + (size_t)(tt & 1) * 64 * LDB;
        const __half* Vc = Vs + (size_t)(tt & 1) * VROWS * LDB;

        if (tt + 1 < nT) {
            uint32_t kd = smem_u32(Ks + (size_t)((tt + 1) & 1) * 64 * LDB);
            uint32_t vd = smem_u32(Vs + (size_t)((tt + 1) & 1) * VROWS * LDB);
            const __half* Kn = Kg + (size_t)(tt + 1) * 64 * 64;
            const __half* Vn = Vg + (size_t)(tt + 1) * 64;
            #pragma unroll
            for (int i = 0; i < 4; i++) {
                int idx = t + i * 128;
                int r = idx >> 3, c = (idx & 7) * 8;
                cp16(kd + (uint32_t)(r * LDB + c) * 2, Kn + r * 64 + c);
                cp16(vd + (uint32_t)(r * LDB + c) * 2, Vn + (size_t)r * M + c);
            }
            CP_COMMIT();
            CP_WAIT(1);
        } else {
            CP_WAIT(0);
        }
        __syncthreads();

        const uint32_t kb = smem_u32(Kc);
        const uint32_t vb = smem_u32(Vc);

        // S = Q K^T
        float Sc[8][2][4] = {};
        #pragma unroll
        for (int jp = 0; jp < 4; jp++) {
            uint32_t Kf[2][8];
            #pragma unroll
            for (int jj = 0; jj < 2; jj++) {
                uint32_t a = kb + (uint32_t)(((jp * 2 + jj) * 8 + lrow) * LDB + lcol) * 2;
                ldsm4(Kf[jj],     a);
                ldsm4(Kf[jj] + 4, a + 64);
            }
            #pragma unroll
            for (int kk = 0; kk < 4; kk++) {
                mma16f(Sc[jp * 2    ][0], Qf[0][kk], Kf[0][kk * 2], Kf[0][kk * 2 + 1]);
                mma16f(Sc[jp * 2    ][1], Qf[1][kk], Kf[0][kk * 2], Kf[0][kk * 2 + 1]);
                mma16f(Sc[jp * 2 + 1][0], Qf[0][kk], Kf[1][kk * 2], Kf[1][kk * 2 + 1]);
                mma16f(Sc[jp * 2 + 1][1], Qf[1][kk], Kf[1][kk * 2], Kf[1][kk * 2 + 1]);
            }
        }

        // exp2 f16x2 -> PV A-fragments
        uint32_t Pa[4][2][4];
        #pragma unroll
        for (int mt = 0; mt < 2; mt++) {
            #pragma unroll
            for (int j = 0; j < 8; j++) {
                int kk = j >> 1, hf = (j & 1) * 2;
                Pa[kk][mt][hf    ] = ex2h2(packh(Sc[j][mt][0], Sc[j][mt][1]));
                Pa[kk][mt][hf + 1] = ex2h2(packh(Sc[j][mt][2], Sc[j][mt][3]));
            }
        }

        // O += P V ; ones rows -> l
        #pragma unroll
        for (int jp = 0; jp < 4; jp++) {
            uint32_t Vf[2][8];
            #pragma unroll
            for (int jj = 0; jj < 2; jj++) {
                uint32_t a = vb + (uint32_t)(((jp * 2 + jj) * 8 + lrow) * LDB + lcol) * 2;
                ldsm4(Vf[jj],     a);
                ldsm4(Vf[jj] + 4, a + 64);
            }
            #pragma unroll
            for (int kk = 0; kk < 4; kk++) {
                mma16f(Of[jp * 2    ][0], Pa[kk][0], Vf[0][kk * 2], Vf[0][kk * 2 + 1]);
                mma16f(Of[jp * 2    ][1], Pa[kk][1], Vf[0][kk * 2], Vf[0][kk * 2 + 1]);
                mma16f(Of[jp * 2 + 1][0], Pa[kk][0], Vf[1][kk * 2], Vf[1][kk * 2 + 1]);
                mma16f(Of[jp * 2 + 1][1], Pa[kk][1], Vf[1][kk * 2], Vf[1][kk * 2 + 1]);
            }
        }
        {
            uint32_t Vf8[8];
            uint32_t a = vb + (uint32_t)((64 + lrow) * LDB + lcol) * 2;
            ldsm4(Vf8,     a);
            ldsm4(Vf8 + 4, a + 64);
            #pragma unroll
            for (int kk = 0; kk < 4; kk++) {
                mma16f(Of[8][0], Pa[kk][0], Vf8[kk * 2], Vf8[kk * 2 + 1]);
                mma16f(Of[8][1], Pa[kk][1], Vf8[kk * 2], Vf8[kk * 2 + 1]);
            }
        }
        __syncthreads();
    }

    // write partial l (col 64 of C-frag lives at tg==0, slots 0/2)
    {
        float* lp = lpart + ((size_t)(split * BB + b) * HH + h) * N + n0;
        if (tg == 0) {
            #pragma unroll
            for (int mt = 0; mt < 2; mt++) {
                lp[wr + mt * 16 + g    ] = Of[8][mt][0];
                lp[wr + mt * 16 + g + 8] = Of[8][mt][2];
            }
        }
    }

    __syncthreads();   // K/V smem dead; reuse as OT [128][68] fp32
    #pragma unroll
    for (int j = 0; j < 8; j++) {
        #pragma unroll
        for (int mt = 0; mt < 2; mt++) {
            int r0 = wr + mt * 16 + g;
            *reinterpret_cast<float2*>(OT + (r0    ) * 68 + j * 8 + 2 * tg) =
                make_float2(Of[j][mt][0], Of[j][mt][1]);
            *reinterpret_cast<float2*>(OT + (r0 + 8) * 68 + j * 8 + 2 * tg) =
                make_float2(Of[j][mt][2], Of[j][mt][3]);
        }
    }
    __syncthreads();

    float* Og = opart + (((size_t)(split * BB + b) * HH + h) * N + n0) * 64;
    #pragma unroll
    for (int it = 0; it < 16; it++) {
        int idx = t + it * 128;
        int n = idx >> 4, di = (idx & 15) * 4;
        *reinterpret_cast<float4*>(Og + (size_t)n * 64 + di) =
            *reinterpret_cast<const float4*>(OT + n * 68 + di);
    }
}

// combine splits: attn[(b*N+n)*256 + h*64+di] = (O0+O1)/(l0+l1), fp16.
__global__ void combine_attn(const float* __restrict__ opart,
                             const float* __restrict__ lpart,
                             __half* __restrict__ attn, int N)
{
    const size_t tot = (size_t)BB * HH * N * 64;
    size_t e = ((size_t)blockIdx.x * 256 + threadIdx.x) * 8;
    if (e >= tot) return;
    int di = (int)(e & 63);
    size_t r = e >> 6;                 // (b*H + h)*N + n
    int n = (int)(r % (size_t)N);
    int bhh = (int)(r / (size_t)N);
    int h = bhh & 3, b = bhh >> 2;

    float4 a0 = *reinterpret_cast<const float4*>(opart + e);
    float4 a1 = *reinterpret_cast<const float4*>(opart + e + 4);
    float4 c0 = *reinterpret_cast<const float4*>(opart + tot + e);
    float4 c1 = *reinterpret_cast<const float4*>(opart + tot + e + 4);
    float inv = 1.0f / (lpart[r] + lpart[(tot >> 6) + r]);

    uint32_t o[4];
    o[0] = packh((a0.x + c0.x) * inv, (a0.y + c0.y) * inv);
    o[1] = packh((a0.z + c0.z) * inv, (a0.w + c0.w) * inv);
    o[2] = packh((a1.x + c1.x) * inv, (a1.y + c1.y) * inv);
    o[3] = packh((a1.z + c1.z) * inv, (a1.w + c1.w) * inv);
    *reinterpret_cast<uint4*>(attn + ((size_t)b * N + n) * DD + h * 64 + di) =
        *reinterpret_cast<uint4*>(o);
}

// ---------------------------------------------------------------------------
// fp16 GEMM body with ldmatrix fragment loads (R11, unchanged).
// ---------------------------------------------------------------------------
#define LDH 40

struct GemmOut {
    float acc[4][4][4];
    int o0, n0, wo, wn, g, tg;
};

__device__ __forceinline__ void gemm_body_h(
    const __half* __restrict__ W, const __half* __restrict__ X0, int S0, int C0,
    const __half* __restrict__ X1, int S1, int b, int IC, int N,
    int o0, int n0, __half* sm, GemmOut& R)
{
    __half* Ws = sm;                   // [2][128][LDH]
    __half* Xs = sm + 2 * 128 * LDH;   // [2][128][LDH]

    const int t  = threadIdx.x;
    const int wid = t >> 5, lane = t & 31;
    R.g = lane >> 2; R.tg = lane & 3;
    R.wo = (wid & 1) * 64;
    R.wn = (wid >> 1) * 32;
    R.o0 = o0; R.n0 = n0;
    const int a_row = (lane & 7) + ((lane >> 3) & 1) * 8;
    const int a_col = (lane >> 4) * 8;
    const int b_row = lane & 7;
    const int b_col = (lane >> 3) * 8;

    auto stage = [&](int buf, int k0) {
        uint32_t wd = smem_u32(Ws + buf * 128 * LDH);
        uint32_t xd = smem_u32(Xs + buf * 128 * LDH);
        #pragma unroll
        for (int i = 0; i < 2; i++) {
            int idx = t + i * 256;
            int r = idx >> 2, c = (idx & 3) * 8;
            cp16(wd + (uint32_t)(r * LDH + c) * 2, W + (size_t)(o0 + r) * IC + k0 + c);
        }
        const __half* xb; int S;
        if (k0 < C0) { xb = X0 + (size_t)b * N * S0 + k0;        S = S0; }
        else         { xb = X1 + (size_t)b * N * S1 + (k0 - C0); S = S1; }
        #pragma unroll
        for (int i = 0; i < 2; i++) {
            int idx = t + i * 256;
            int r = idx >> 2, c = (idx & 3) * 8;
            cp16(xd + (uint32_t)(r * LDH + c) * 2, xb + (size_t)(n0 + r) * S + c);
        }
        CP_COMMIT();
    };

    stage(0, 0);
    #pragma unroll
    for (int a = 0; a < 4; a++)
        #pragma unroll
        for (int c = 0; c < 4; c++)
            #pragma unroll
            for (int d = 0; d < 4; d++) R.acc[a][c][d] = 0.f;

    const int nK = IC / 32;
    for (int kt = 0; kt < nK; kt++) {
        if (kt + 1 < nK) { stage((kt + 1) & 1, (kt + 1) * 32); CP_WAIT(1); }
        else             { CP_WAIT(0); }
        __syncthreads();
        const uint32_t wb = smem_u32(Ws + (kt & 1) * 128 * LDH);
        const uint32_t xb = smem_u32(Xs + (kt & 1) * 128 * LDH);

        uint32_t Bf[4][4];
        #pragma unroll
        for (int nt = 0; nt < 4; nt++)
            ldsm4(Bf[nt], xb + (uint32_t)((R.wn + nt * 8 + b_row) * LDH + b_col) * 2);

        #pragma unroll
        for (int ks = 0; ks < 2; ks++) {
            uint32_t Af[4][4];
            #pragma unroll
            for (int mt = 0; mt < 4; mt++)
                ldsm4(Af[mt], wb + (uint32_t)((R.wo + mt * 16 + a_row) * LDH
                                              + ks * 16 + a_col) * 2);
            #pragma unroll
            for (int nt = 0; nt < 4; nt++)
                #pragma unroll
                for (int mt = 0; mt < 4; mt++)
                    mma16f(R.acc[mt][nt], Af[mt], Bf[nt][ks * 2], Bf[nt][ks * 2 + 1]);
        }
        __syncthreads();
    }
}

// generic projection. mode 0: fp32 (B,OC,N); mode 1: fp16 (B,OC,N).
__global__ void __launch_bounds__(256)
gemm_h(const __half* __restrict__ W, const float* __restrict__ bias,
       const __half* __restrict__ X0, int S0, int C0,
       const __half* __restrict__ X1, int S1,
       void* __restrict__ out, int OC, int IC, int N, int mode)
{
    extern __shared__ __half smh[];
    GemmOut R;
    gemm_body_h(W, X0, S0, C0, X1, S1, blockIdx.z, IC, N,
                blockIdx.y * 128, blockIdx.x * 128, smh, R);

    #pragma unroll
    for (int mt = 0; mt < 4; mt++) {
        int o_g  = R.o0 + R.wo + mt * 16 + R.g;
        int o_g8 = o_g + 8;
        float bg  = bias[o_g];
        float bg8 = bias[o_g8];
        #pragma unroll
        for (int nt = 0; nt < 4; nt++) {
            int n = R.n0 + R.wn + nt * 8 + 2 * R.tg;
            float c0 = R.acc[mt][nt][0] + bg,  c1 = R.acc[mt][nt][1] + bg;
            float c2 = R.acc[mt][nt][2] + bg8, c3 = R.acc[mt][nt][3] + bg8;
            if (mode == 0) {
                float* o32 = (float*)out;
                *reinterpret_cast<float2*>(o32 + ((size_t)blockIdx.z * OC + o_g ) * N + n) =
                    make_float2(c0, c1);
                *reinterpret_cast<float2*>(o32 + ((size_t)blockIdx.z * OC + o_g8) * N + n) =
                    make_float2(c2, c3);
            } else {
                __half* o16 = (__half*)out;
                *reinterpret_cast<uint32_t*>(o16 + ((size_t)blockIdx.z * OC + o_g ) * N + n) =
                    packh(c0, c1);
                *reinterpret_cast<uint32_t*>(o16 + ((size_t)blockIdx.z * OC + o_g8) * N + n) =
                    packh(c2, c3);
            }
        }
    }
}

// fused Q/K/V projection with smem-staged coalesced epilogue for q/k.
__global__ void __launch_bounds__(256)
gemm_qkv(const __half* __restrict__ wts,
         const float* __restrict__ bq, const float* __restrict__ bk,
         const float* __restrict__ bv,
         const __half* __restrict__ xt, const __half* __restrict__ st,
         __half* __restrict__ qp, __half* __restrict__ kp,
         __half* __restrict__ vp, int N)
{
    extern __shared__ __half smh[];
    const int z = blockIdx.z;
    const int which = z >> 1;
    const int b = z & 1;
    const __half* W    = wts + which * 65536;
    const float* bias  = (which == 0) ? bq : (which == 1) ? bk : bv;
    const __half* X    = (which == 0) ? xt : st;
    const float oscale = (which == 0) ? QSCALE : 1.0f;

    GemmOut R;
    gemm_body_h(W, X, DD, DD, nullptr, DD, b, DD, N,
                blockIdx.y * 128, blockIdx.x * 128, smh, R);

    const int t = threadIdx.x;

    if (which < 2) {
        __half* St = smh;
        __syncthreads();
        #pragma unroll
        for (int mt = 0; mt < 4; mt++) {
            int ol  = R.wo + mt * 16 + R.g;
            int ol8 = ol + 8;
            float bg  = bias[R.o0 + ol];
            float bg8 = bias[R.o0 + ol8];
            int col  = (ol  & 3) * 32 + (ol  >> 2);
            int col8 = (ol8 & 3) * 32 + (ol8 >> 2);
            #pragma unroll
            for (int nt = 0; nt < 4; nt++) {
                int nl = R.wn + nt * 8 + 2 * R.tg;
                St[(nl    ) * 136 + col ] = __float2half_rn((R.acc[mt][nt][0] + bg)  * oscale);
                St[(nl + 1) * 136 + col ] = __float2half_rn((R.acc[mt][nt][1] + bg)  * oscale);
                St[(nl    ) * 136 + col8] = __float2half_rn((R.acc[mt][nt][2] + bg8) * oscale);
                St[(nl + 1) * 136 + col8] = __float2half_rn((R.acc[mt][nt][3] + bg8) * oscale);
            }
        }
        __syncthreads();

        __half* out = (which == 0) ? qp : kp;
        const int di0 = R.o0 >> 2;
        #pragma unroll
        for (int it = 0; it < 8; it++) {
            int idx = t + it * 256;
            int quad = idx & 3, pr = idx >> 2;
            int hh = pr >> 7, nl = pr & 127;
            uint4 val = *reinterpret_cast<const uint4*>(St + nl * 136 + hh * 32 + quad * 8);
            *reinterpret_cast<uint4*>(
                out + (((size_t)b * HH + hh) * N + R.n0 + nl) * 64 + di0 + quad * 8) = val;
        }
    } else {
        #pragma unroll
        for (int mt = 0; mt < 4; mt++) {
            int o_g  = R.o0 + R.wo + mt * 16 + R.g;
            int o_g8 = o_g + 8;
            float bg  = bias[o_g];
            float bg8 = bias[o_g8];
            #pragma unroll
            for (int nt = 0; nt < 4; nt++) {
                int n = R.n0 + R.wn + nt * 8 + 2 * R.tg;
                int h0 = o_g & 3,  d0 = o_g >> 2;
                int h1 = o_g8 & 3, d1 = o_g8 >> 2;
                *reinterpret_cast<uint32_t*>(
                    vp + (((size_t)b * HH + h0) * 64 + d0) * N + n) =
                    packh(R.acc[mt][nt][0] + bg, R.acc[mt][nt][1] + bg);
                *reinterpret_cast<uint32_t*>(
                    vp + (((size_t)b * HH + h1) * 64 + d1) * N + n) =
                    packh(R.acc[mt][nt][2] + bg8, R.acc[mt][nt][3] + bg8);
            }
        }
    }
}

// ---------------------------------------------------------------------------
// InstanceNorm stats + normalize/transpose
// ---------------------------------------------------------------------------
__global__ void inst_stats(const __half* __restrict__ hb, float* __restrict__ stats, int N)
{
    int row = blockIdx.x;
    const __half* p = hb + (size_t)row * N;

    float s = 0.f, s2 = 0.f;
    for (int i = threadIdx.x * 8; i < N; i += 256 * 8) {
        uint4 raw = *reinterpret_cast<const uint4*>(p + i);
        const __half2* h2 = reinterpret_cast<const __half2*>(&raw);
        #pragma unroll
        for (int kk = 0; kk < 4; kk++) {
            float2 f = __half22float2(h2[kk]);
            s  += f.x + f.y;
            s2 += f.x * f.x + f.y * f.y;
        }
    }
    #pragma unroll
    for (int off = 16; off > 0; off >>= 1) {
        s  += __shfl_xor_sync(0xffffffffu, s,  off);
        s2 += __shfl_xor_sync(0xffffffffu, s2, off);
    }
    __shared__ float sh[16];
    int wid = threadIdx.x >> 5, lid = threadIdx.x & 31;
    if (lid == 0) { sh[wid] = s; sh[wid + 8] = s2; }
    __syncthreads();
    if (threadIdx.x == 0) {
        s = 0.f; s2 = 0.f;
        #pragma unroll
        for (int w = 0; w < 8; w++) { s += sh[w]; s2 += sh[w + 8]; }
        float mean = s / (float)N;
        float var  = s2 / (float)N - mean * mean;
        stats[row * 2]     = mean;
        stats[row * 2 + 1] = rsqrtf(var + 1e-5f);
    }
}

__global__ void norm_transpose(const __half* __restrict__ hb, const float* __restrict__ stats,
                               __half* __restrict__ ht, int N)
{
    __shared__ __half tile[32][33];
    const int b = blockIdx.z;
    const int c0 = blockIdx.y * 32, n0 = blockIdx.x * 32;
    const int tx = threadIdx.x & 31, ty = threadIdx.x >> 5;

    #pragma unroll
    for (int i = 0; i < 4; i++) {
        int c = ty + i * 8;
        int row = b * 512 + c0 + c;
        float mu  = stats[row * 2];
        float inv = stats[row * 2 + 1];
        float v = __half2float(hb[(size_t)row * N + n0 + tx]);
        tile[c][tx] = __float2half_rn(fmaxf(0.f, (v - mu) * inv));
    }
    __syncthreads();
    #pragma unroll
    for (int i = 0; i < 4; i++) {
        int n = ty + i * 8;
        ht[((size_t)b * N + n0 + n) * 512 + c0 + tx] = tile[tx][n];
    }
}

// ---------------------------------------------------------------------------
extern "C" void kernel_launch(void* const* d_in, const int* in_sizes, int n_in,
                              void* d_out, int out_size)
{
    const float* x   = (const float*)d_in[0];
    const float* src = (const float*)d_in[1];
    const float* Wq  = (const float*)d_in[2];
    const float* bq  = (const float*)d_in[3];
    const float* Wk  = (const float*)d_in[4];
    const float* bk  = (const float*)d_in[5];
    const float* Wv  = (const float*)d_in[6];
    const float* bv  = (const float*)d_in[7];
    const float* Wm  = (const float*)d_in[8];
    const float* bm  = (const float*)d_in[9];
    const float* W1  = (const float*)d_in[10];
    const float* b1  = (const float*)d_in[11];
    const float* W2  = (const float*)d_in[12];
    const float* b2  = (const float*)d_in[13];

    const int B = BB, D = DD;
    const int N = in_sizes[0] / (B * D);
    const int M = in_sizes[1] / (B * D);

    __half *qp, *kp, *vp, *xtp, *stp, *attnp, *hp, *htp, *wts, *wcat;
    float *bf, *stats, *opart, *lpart;
    cudaGetSymbolAddress((void**)&qp,    g_q);
    cudaGetSymbolAddress((void**)&kp,    g_k);
    cudaGetSymbolAddress((void**)&vp,    g_v);
    cudaGetSymbolAddress((void**)&xtp,   g_xt);
    cudaGetSymbolAddress((void**)&stp,   g_st);
    cudaGetSymbolAddress((void**)&attnp, g_attn);
    cudaGetSymbolAddress((void**)&hp,    g_h);
    cudaGetSymbolAddress((void**)&htp,   g_ht);
    cudaGetSymbolAddress((void**)&wts,   g_wts);
    cudaGetSymbolAddress((void**)&wcat,  g_wcat);
    cudaGetSymbolAddress((void**)&bf,    g_bf);
    cudaGetSymbolAddress((void**)&stats, g_stats);
    cudaGetSymbolAddress((void**)&opart, g_opart);
    cudaGetSymbolAddress((void**)&lpart, g_lpart);

    const int gsmem = 4 * 128 * LDH * (int)sizeof(__half);   // 40960
    const int fsmem = 18432 + 20736 + 18432;                  // 57600
    cudaFuncSetAttribute(gemm_h,   cudaFuncAttributeMaxDynamicSharedMemorySize, gsmem);
    cudaFuncSetAttribute(gemm_qkv, cudaFuncAttributeMaxDynamicSharedMemorySize, gsmem);
    cudaFuncSetAttribute(flash_attn_fp16, cudaFuncAttributeMaxDynamicSharedMemorySize, fsmem);

    // 0. producers
    round_weights<<<(655360 + 255) / 256, 256>>>(Wq, Wk, Wv, Wm, W1, W2, wts);
    transpose_in<<<dim3(N / 32, D / 32, 2 * B), 256>>>(x, src, xtp, stp, N);
    fuse_w1<<<512, 256>>>(wts, b1, bm, wcat, bf);

    // 1. fused Q/K/V projections
    gemm_qkv<<<dim3(N / 128, D / 128, 3 * B), 256, gsmem>>>(
        wts, bq, bk, bv, xtp, stp, qp, kp, vp, N);

    // 2. split-K flash attention -> fp32 partials, then combine -> attn fp16
    flash_attn_fp16<<<dim3(N / 128, HH, 2 * B), 128, fsmem>>>(
        qp, kp, vp, opart, lpart, N, M);
    combine_attn<<<(B * HH * N * 64) / (256 * 8), 256>>>(opart, lpart, attnp, N);

    // 3. fused W1 layer -> h (B,2D,N) fp16
    gemm_h<<<dim3(N / 128, (2 * D) / 128, B), 256, gsmem>>>(
        wcat, bf, xtp, D, D, attnp, D, hp, 2 * D, 2 * D, N, 1);

    // 4. InstanceNorm stats + normalize/transpose -> ht (B,N,512)
    inst_stats<<<B * 2 * D, 256>>>(hp, stats, N);
    norm_transpose<<<dim3(N / 32, (2 * D) / 32, B), 256>>>(hp, stats, htp, N);

    // 5. final projection -> d_out (B,D,N) fp32
    gemm_h<<<dim3(N / 128, D / 128, B), 256, gsmem>>>(
        wts + OFF_W2, b2, htp, 2 * D, 2 * D, nullptr, 2 * D, d_out, D, 2 * D, N, 0);
}

// round 15
// speedup vs baseline: 1.1287x; 1.1287x over previous
#include <cuda_runtime.h>
#include <cuda_fp16.h>
#include <cstdint>
#include <cstddef>

// ---------------------------------------------------------------------------
// AttentionalPropagation, B=2, D=256, H=4, dim=64, N=M=4096.
// R15: R11 flash (best known) restored verbatim; producers fused into one
//      launch; GEMM BK=32 -> 64 (half the barriers/waits).
// ---------------------------------------------------------------------------

#define BB 2
#define DD 256
#define HH 4

__device__ __half g_q[BB * HH * 4096 * 64];   // [b][h][n][di], pre-scaled
__device__ __half g_k[BB * HH * 4096 * 64];   // [b][h][m][di]
__device__ __half g_v[BB * HH * 64 * 4096];   // [b][h][di][m] (transposed)
__device__ __half g_xt  [BB * 4096 * DD];     // x  transposed (B,N,256) fp16
__device__ __half g_st  [BB * 4096 * DD];     // src transposed
__device__ __half g_attn[BB * 4096 * DD];     // attn (B,N,256), ch = h*64+di
__device__ __half g_h   [BB * 2 * DD * 4096]; // (B,2D,N) fp16 (pre-norm)
__device__ __half g_ht  [BB * 4096 * 2 * DD]; // (B,N,512) fp16 (post-norm)
__device__ __half g_wts [655360];             // fp16 weights
__device__ __half g_wcat[512 * 512];          // [W1x | perm(W1m@Wm)] fp16
__device__ float  g_bf  [512];                // W1m@bm + b1
__device__ float  g_stats[BB * 2 * DD * 2];   // per (b,c): mean, inv

#define OFF_WQ 0
#define OFF_WK 65536
#define OFF_WV 131072
#define OFF_WM 196608
#define OFF_W1 262144
#define OFF_W2 524288

#define QSCALE (0.125f * 1.44269504088896340736f)

// ============================ PTX helpers ==================================
__device__ __forceinline__ uint32_t smem_u32(const void* p) {
    uint32_t a;
    asm("{ .reg .u64 t; cvta.to.shared.u64 t, %1; cvt.u32.u64 %0, t; }"
        : "=r"(a) : "l"(p));
    return a;
}
__device__ __forceinline__ uint32_t packh(float lo, float hi) {
    __half2 h = __floats2half2_rn(lo, hi);
    return *reinterpret_cast<uint32_t*>(&h);
}
__device__ __forceinline__ uint32_t ex2h2(uint32_t h2) {
    uint32_t r; asm("ex2.approx.f16x2 %0, %1;" : "=r"(r) : "r"(h2)); return r;
}
__device__ __forceinline__ void mma16f(float* d, const uint32_t* a,
                                       uint32_t b0, uint32_t b1) {
    asm volatile("mma.sync.aligned.m16n8k16.row.col.f32.f16.f16.f32 "
        "{%0,%1,%2,%3}, {%4,%5,%6,%7}, {%8,%9}, {%0,%1,%2,%3};"
        : "+f"(d[0]), "+f"(d[1]), "+f"(d[2]), "+f"(d[3])
        : "r"(a[0]), "r"(a[1]), "r"(a[2]), "r"(a[3]), "r"(b0), "r"(b1));
}
__device__ __forceinline__ void ldsm4(uint32_t* r, uint32_t addr) {
    asm volatile("ldmatrix.sync.aligned.m8n8.x4.shared.b16 {%0,%1,%2,%3}, [%4];"
        : "=r"(r[0]), "=r"(r[1]), "=r"(r[2]), "=r"(r[3]) : "r"(addr));
}
__device__ __forceinline__ void cp16(uint32_t s, const void* g) {
    asm volatile("cp.async.ca.shared.global [%0], [%1], 16;" :: "r"(s), "l"(g));
}
#define CP_COMMIT() asm volatile("cp.async.commit_group;" ::: "memory")
#define CP_WAIT(n)  asm volatile("cp.async.wait_group %0;" :: "n"(n) : "memory")

// ---------------------------------------------------------------------------
// Fused producers: one launch does weight fp16 conversion, input transpose,
// and the W1 message-fold (fold computed from fp32 originals — independent).
// Block dispatch by flat blockIdx.x.
// ---------------------------------------------------------------------------
__global__ void producers(const float* __restrict__ wq, const float* __restrict__ wk,
                          const float* __restrict__ wv, const float* __restrict__ wm,
                          const float* __restrict__ w1, const float* __restrict__ w2,
                          __half* __restrict__ wts,
                          const float* __restrict__ x, const float* __restrict__ src,
                          __half* __restrict__ xt, __half* __restrict__ st,
                          const float* __restrict__ b1, const float* __restrict__ bm,
                          __half* __restrict__ wcat, float* __restrict__ bf, int N)
{
    __shared__ __half tile[32][33];
    const int bx = blockIdx.x;
    const int nWB = 2560;                 // 655360 / 256
    const int nx  = N / 32;
    const int nTB = nx * 8 * 4;

    if (bx < nWB) {
        // --- weight conversion ---
        int i = bx * 256 + threadIdx.x;
        float v;
        if      (i < OFF_WK) v = wq[i - OFF_WQ];
        else if (i < OFF_WV) v = wk[i - OFF_WK];
        else if (i < OFF_WM) v = wv[i - OFF_WV];
        else if (i < OFF_W1) v = wm[i - OFF_WM];
        else if (i < OFF_W2) v = w1[i - OFF_W1];
        else                 v = w2[i - OFF_W2];
        wts[i] = __float2half_rn(v);
    } else if (bx < nWB + nTB) {
        // --- input transpose (B,256,N) fp32 -> (B,N,256) fp16 ---
        int f = bx - nWB;
        int cx = f % nx;
        int rest = f / nx;
        int cy = rest & 7;
        int zz = rest >> 3;
        const int which = zz >> 1, b = zz & 1;
        const float* in = which ? src : x;
        __half* out = which ? st : xt;
        const int c0 = cy * 32, n0 = cx * 32;
        const int tx = threadIdx.x & 31, ty = threadIdx.x >> 5;

        #pragma unroll
        for (int i = 0; i < 4; i++) {
            int c = ty + i * 8;
            tile[c][tx] = __float2half_rn(in[((size_t)(b * DD + c0 + c)) * N + n0 + tx]);
        }
        __syncthreads();
        #pragma unroll
        for (int i = 0; i < 4; i++) {
            int n = ty + i * 8;
            out[((size_t)b * N + n0 + n) * DD + c0 + tx] = tile[tx][n];
        }
    } else {
        // --- W1 fold from fp32 originals: Wcat = [W1x | perm(W1m@Wm)] ---
        int o = bx - nWB - nTB;
        int j = threadIdx.x;

        wcat[o * 512 + j] = __float2half_rn(w1[o * 512 + j]);

        float acc = 0.f;
        const float* w1m = w1 + o * 512 + 256;
        #pragma unroll 8
        for (int kk = 0; kk < 256; kk++)
            acc = fmaf(w1m[kk], wm[kk * 256 + j], acc);
        int jp = (j & 3) * 64 + (j >> 2);
        wcat[o * 512 + 256 + jp] = __float2half_rn(acc);

        if (j == 0) {
            float b = b1[o];
            for (int kk = 0; kk < 256; kk++) b = fmaf(w1m[kk], bm[kk], b);
            bf[o] = b;
        }
    }
}

// ---------------------------------------------------------------------------
// fp16 flash attention (R11, unchanged: best known configuration).
// 4 warps x 32 q-rows; ldmatrix K/V; ex2.f16x2 softmax; tensor row-sum.
// grid (N/128, H, B), 128 threads.
// ---------------------------------------------------------------------------
#define LDB   72
#define VROWS 72

__global__ void __launch_bounds__(128)
flash_attn_fp16(const __half* __restrict__ q, const __half* __restrict__ k,
                const __half* __restrict__ v, __half* __restrict__ attn,
                int N, int M)
{
    extern __shared__ char smb[];
    __half* Ks = reinterpret_cast<__half*>(smb);             // [2][64][LDB]
    __half* Vs = reinterpret_cast<__half*>(smb + 18432);     // [2][VROWS][LDB]
    __half* Qs = reinterpret_cast<__half*>(smb + 39168);     // [128][LDB]
    __half* OTh = reinterpret_cast<__half*>(smb);            // [128][72] epilogue

    const int b  = blockIdx.z, h = blockIdx.y;
    const int n0 = blockIdx.x * 128;
    const int bh = b * HH + h;
    const int t  = threadIdx.x;
    const int wid = t >> 5, lane = t & 31;
    const int g = lane >> 2, tg = lane & 3;
    const int wr = wid * 32;
    const int lrow = lane & 7;
    const int lcol = (lane >> 3) * 8;

    const __half* Kg = k + (size_t)bh * M * 64;
    const __half* Vg = v + (size_t)bh * 64 * M;

    {
        uint32_t kd = smem_u32(Ks), vd = smem_u32(Vs);
        #pragma unroll
        for (int i = 0; i < 4; i++) {
            int idx = t + i * 128;
            int r = idx >> 3, c = (idx & 7) * 8;
            cp16(kd + (uint32_t)(r * LDB + c) * 2, Kg + r * 64 + c);
            cp16(vd + (uint32_t)(r * LDB + c) * 2, Vg + (size_t)r * M + c);
        }
        CP_COMMIT();
    }

    // ones/zeros rows 64..71 of both V buffers
    {
        const __half one = __float2half(1.0f);
        const __half zer = __float2half(0.0f);
        for (int i = t; i < 2 * 8 * LDB; i += 128) {
            int buf = i / (8 * LDB);
            int rem = i - buf * 8 * LDB;
            int r = rem / LDB, c = rem - r * LDB;
            Vs[(size_t)buf * VROWS * LDB + (64 + r) * LDB + c] = (r == 0) ? one : zer;
        }
    }

    // stage Q
    {
        const __half* Qg = q + ((size_t)bh * N + n0) * 64;
        #pragma unroll
        for (int i = 0; i < 8; i++) {
            int idx = t + i * 128;
            int r = idx >> 3, c = (idx & 7) * 8;
            *reinterpret_cast<uint4*>(Qs + r * LDB + c) =
                *reinterpret_cast<const uint4*>(Qg + r * 64 + c);
        }
    }
    __syncthreads();

    // persistent Q fragments
    uint32_t Qf[2][4][4];
    #pragma unroll
    for (int mt = 0; mt < 2; mt++) {
        int r0 = wr + mt * 16 + g;
        #pragma unroll
        for (int kk = 0; kk < 4; kk++) {
            Qf[mt][kk][0] = *reinterpret_cast<uint32_t*>(Qs + (r0    ) * LDB + kk * 16 + 2 * tg);
            Qf[mt][kk][1] = *reinterpret_cast<uint32_t*>(Qs + (r0 + 8) * LDB + kk * 16 + 2 * tg);
            Qf[mt][kk][2] = *reinterpret_cast<uint32_t*>(Qs + (r0    ) * LDB + kk * 16 + 2 * tg + 8);
            Qf[mt][kk][3] = *reinterpret_cast<uint32_t*>(Qs + (r0 + 8) * LDB + kk * 16 + 2 * tg + 8);
        }
    }
    __syncthreads();

    float Of[9][2][4] = {};     // Of[8] = l accumulators via ones column

    const int nT = M / 64;
    for (int tt = 0; tt < nT; tt++) {
        const __half* Kc = Ks + (size_t)(tt & 1) * 64 * LDB;
        const __half* Vc = Vs + (size_t)(tt & 1) * VROWS * LDB;

        if (tt + 1 < nT) {
            uint32_t kd = smem_u32(Ks + (size_t)((tt + 1) & 1) * 64 * LDB);
            uint32_t vd = smem_u32(Vs + (size_t)((tt + 1) & 1) * VROWS * LDB);
            const __half* Kn = Kg + (size_t)(tt + 1) * 64 * 64;
            const __half* Vn = Vg + (size_t)(tt + 1) * 64;
            #pragma unroll
            for (int i = 0; i < 4; i++) {
                int idx = t + i * 128;
                int r = idx >> 3, c = (idx & 7) * 8;
                cp16(kd + (uint32_t)(r * LDB + c) * 2, Kn + r * 64 + c);
                cp16(vd + (uint32_t)(r * LDB + c) * 2, Vn + (size_t)r * M + c);
            }
            CP_COMMIT();
            CP_WAIT(1);
        } else {
            CP_WAIT(0);
        }
        __syncthreads();

        const uint32_t kb = smem_u32(Kc);
        const uint32_t vb = smem_u32(Vc);

        // S = Q K^T
        float Sc[8][2][4] = {};
        #pragma unroll
        for (int jp = 0; jp < 4; jp++) {
            uint32_t Kf[2][8];
            #pragma unroll
            for (int jj = 0; jj < 2; jj++) {
                uint32_t a = kb + (uint32_t)(((jp * 2 + jj) * 8 + lrow) * LDB + lcol) * 2;
                ldsm4(Kf[jj],     a);
                ldsm4(Kf[jj] + 4, a + 64);
            }
            #pragma unroll
            for (int kk = 0; kk < 4; kk++) {
                mma16f(Sc[jp * 2    ][0], Qf[0][kk], Kf[0][kk * 2], Kf[0][kk * 2 + 1]);
                mma16f(Sc[jp * 2    ][1], Qf[1][kk], Kf[0][kk * 2], Kf[0][kk * 2 + 1]);
                mma16f(Sc[jp * 2 + 1][0], Qf[0][kk], Kf[1][kk * 2], Kf[1][kk * 2 + 1]);
                mma16f(Sc[jp * 2 + 1][1], Qf[1][kk], Kf[1][kk * 2], Kf[1][kk * 2 + 1]);
            }
        }

        // exp2 f16x2 -> PV A-fragments
        uint32_t Pa[4][2][4];
        #pragma unroll
        for (int mt = 0; mt < 2; mt++) {
            #pragma unroll
            for (int j = 0; j < 8; j++) {
                int kk = j >> 1, hf = (j & 1) * 2;
                Pa[kk][mt][hf    ] = ex2h2(packh(Sc[j][mt][0], Sc[j][mt][1]));
                Pa[kk][mt][hf + 1] = ex2h2(packh(Sc[j][mt][2], Sc[j][mt][3]));
            }
        }

        // O += P V ; ones rows -> l
        #pragma unroll
        for (int jp = 0; jp < 4; jp++) {
            uint32_t Vf[2][8];
            #pragma unroll
            for (int jj = 0; jj < 2; jj++) {
                uint32_t a = vb + (uint32_t)(((jp * 2 + jj) * 8 + lrow) * LDB + lcol) * 2;
                ldsm4(Vf[jj],     a);
                ldsm4(Vf[jj] + 4, a + 64);
            }
            #pragma unroll
            for (int kk = 0; kk < 4; kk++) {
                mma16f(Of[jp * 2    ][0], Pa[kk][0], Vf[0][kk * 2], Vf[0][kk * 2 + 1]);
                mma16f(Of[jp * 2    ][1], Pa[kk][1], Vf[0][kk * 2], Vf[0][kk * 2 + 1]);
                mma16f(Of[jp * 2 + 1][0], Pa[kk][0], Vf[1][kk * 2], Vf[1][kk * 2 + 1]);
                mma16f(Of[jp * 2 + 1][1], Pa[kk][1], Vf[1][kk * 2], Vf[1][kk * 2 + 1]);
            }
        }
        {
            uint32_t Vf8[8];
            uint32_t a = vb + (uint32_t)((64 + lrow) * LDB + lcol) * 2;
            ldsm4(Vf8,     a);
            ldsm4(Vf8 + 4, a + 64);
            #pragma unroll
            for (int kk = 0; kk < 4; kk++) {
                mma16f(Of[8][0], Pa[kk][0], Vf8[kk * 2], Vf8[kk * 2 + 1]);
                mma16f(Of[8][1], Pa[kk][1], Vf8[kk * 2], Vf8[kk * 2 + 1]);
            }
        }
        __syncthreads();
    }

    float linv[2][2];
    #pragma unroll
    for (int mt = 0; mt < 2; mt++) {
        float l0 = __shfl_sync(0xffffffffu, Of[8][mt][0], lane & ~3);
        float l1 = __shfl_sync(0xffffffffu, Of[8][mt][2], lane & ~3);
        linv[mt][0] = 1.0f / l0;
        linv[mt][1] = 1.0f / l1;
    }

    __syncthreads();   // K/V smem dead; reuse as OTh [128 n][72 di]
    #pragma unroll
    for (int j = 0; j < 8; j++) {
        #pragma unroll
        for (int mt = 0; mt < 2; mt++) {
            int r0 = wr + mt * 16 + g;
            *reinterpret_cast<uint32_t*>(OTh + (r0    ) * 72 + j * 8 + 2 * tg) =
                packh(Of[j][mt][0] * linv[mt][0], Of[j][mt][1] * linv[mt][0]);
            *reinterpret_cast<uint32_t*>(OTh + (r0 + 8) * 72 + j * 8 + 2 * tg) =
                packh(Of[j][mt][2] * linv[mt][1], Of[j][mt][3] * linv[mt][1]);
        }
    }
    __syncthreads();

    __half* Ag = attn + ((size_t)b * N + n0) * DD + h * 64;
    #pragma unroll
    for (int it = 0; it < 8; it++) {
        int n = it * 16 + (t >> 3);
        int qd = (t & 7) * 8;
        uint4 val = *reinterpret_cast<const uint4*>(OTh + n * 72 + qd);
        *reinterpret_cast<uint4*>(Ag + (size_t)n * DD + qd) = val;
    }
}

// ---------------------------------------------------------------------------
// fp16 GEMM body, BK=64 (half the barriers of R11), ldmatrix fragment loads.
// Tile 128x128; 8 warps = 2(o) x 4(n), warp tile 64x32.
// Both smem tiles [2][128][LDH2] k-contiguous fp16.
// ---------------------------------------------------------------------------
#define LDH2 72

struct GemmOut {
    float acc[4][4][4];
    int o0, n0, wo, wn, g, tg;
};

__device__ __forceinline__ void gemm_body_h(
    const __half* __restrict__ W, const __half* __restrict__ X0, int S0, int C0,
    const __half* __restrict__ X1, int S1, int b, int IC, int N,
    int o0, int n0, __half* sm, GemmOut& R)
{
    __half* Ws = sm;                    // [2][128][LDH2]
    __half* Xs = sm + 2 * 128 * LDH2;   // [2][128][LDH2]

    const int t  = threadIdx.x;
    const int wid = t >> 5, lane = t & 31;
    R.g = lane >> 2; R.tg = lane & 3;
    R.wo = (wid & 1) * 64;
    R.wn = (wid >> 1) * 32;
    R.o0 = o0; R.n0 = n0;
    const int a_row = (lane & 7) + ((lane >> 3) & 1) * 8;
    const int a_col = (lane >> 4) * 8;
    const int b_row = lane & 7;
    const int b_col = (lane >> 3) * 8;

    auto stage = [&](int buf, int k0) {
        uint32_t wd = smem_u32(Ws + buf * 128 * LDH2);
        uint32_t xd = smem_u32(Xs + buf * 128 * LDH2);
        #pragma unroll
        for (int i = 0; i < 4; i++) {
            int idx = t + i * 256;
            int r = idx >> 3, c = (idx & 7) * 8;
            cp16(wd + (uint32_t)(r * LDH2 + c) * 2, W + (size_t)(o0 + r) * IC + k0 + c);
        }
        const __half* xb; int S;
        if (k0 < C0) { xb = X0 + (size_t)b * N * S0 + k0;        S = S0; }
        else         { xb = X1 + (size_t)b * N * S1 + (k0 - C0); S = S1; }
        #pragma unroll
        for (int i = 0; i < 4; i++) {
            int idx = t + i * 256;
            int r = idx >> 3, c = (idx & 7) * 8;
            cp16(xd + (uint32_t)(r * LDH2 + c) * 2, xb + (size_t)(n0 + r) * S + c);
        }
        CP_COMMIT();
    };

    stage(0, 0);
    #pragma unroll
    for (int a = 0; a < 4; a++)
        #pragma unroll
        for (int c = 0; c < 4; c++)
            #pragma unroll
            for (int d = 0; d < 4; d++) R.acc[a][c][d] = 0.f;

    const int nK = IC / 64;
    for (int kt = 0; kt < nK; kt++) {
        if (kt + 1 < nK) { stage((kt + 1) & 1, (kt + 1) * 64); CP_WAIT(1); }
        else             { CP_WAIT(0); }
        __syncthreads();
        const uint32_t wb = smem_u32(Ws + (kt & 1) * 128 * LDH2);
        const uint32_t xb = smem_u32(Xs + (kt & 1) * 128 * LDH2);

        #pragma unroll
        for (int h2 = 0; h2 < 2; h2++) {        // two 32-k halves
            uint32_t Bf[4][4];
            #pragma unroll
            for (int nt = 0; nt < 4; nt++)
                ldsm4(Bf[nt], xb + (uint32_t)((R.wn + nt * 8 + b_row) * LDH2
                                              + h2 * 32 + b_col) * 2);
            #pragma unroll
            for (int ks = 0; ks < 2; ks++) {
                uint32_t Af[4][4];
                #pragma unroll
                for (int mt = 0; mt < 4; mt++)
                    ldsm4(Af[mt], wb + (uint32_t)((R.wo + mt * 16 + a_row) * LDH2
                                                  + h2 * 32 + ks * 16 + a_col) * 2);
                #pragma unroll
                for (int nt = 0; nt < 4; nt++)
                    #pragma unroll
                    for (int mt = 0; mt < 4; mt++)
                        mma16f(R.acc[mt][nt], Af[mt], Bf[nt][ks * 2], Bf[nt][ks * 2 + 1]);
            }
        }
        __syncthreads();
    }
}

// generic projection. mode 0: fp32 (B,OC,N); mode 1: fp16 (B,OC,N).
__global__ void __launch_bounds__(256)
gemm_h(const __half* __restrict__ W, const float* __restrict__ bias,
       const __half* __restrict__ X0, int S0, int C0,
       const __half* __restrict__ X1, int S1,
       void* __restrict__ out, int OC, int IC, int N, int mode)
{
    extern __shared__ __half smh[];
    GemmOut R;
    gemm_body_h(W, X0, S0, C0, X1, S1, blockIdx.z, IC, N,
                blockIdx.y * 128, blockIdx.x * 128, smh, R);

    #pragma unroll
    for (int mt = 0; mt < 4; mt++) {
        int o_g  = R.o0 + R.wo + mt * 16 + R.g;
        int o_g8 = o_g + 8;
        float bg  = bias[o_g];
        float bg8 = bias[o_g8];
        #pragma unroll
        for (int nt = 0; nt < 4; nt++) {
            int n = R.n0 + R.wn + nt * 8 + 2 * R.tg;
            float c0 = R.acc[mt][nt][0] + bg,  c1 = R.acc[mt][nt][1] + bg;
            float c2 = R.acc[mt][nt][2] + bg8, c3 = R.acc[mt][nt][3] + bg8;
            if (mode == 0) {
                float* o32 = (float*)out;
                *reinterpret_cast<float2*>(o32 + ((size_t)blockIdx.z * OC + o_g ) * N + n) =
                    make_float2(c0, c1);
                *reinterpret_cast<float2*>(o32 + ((size_t)blockIdx.z * OC + o_g8) * N + n) =
                    make_float2(c2, c3);
            } else {
                __half* o16 = (__half*)out;
                *reinterpret_cast<uint32_t*>(o16 + ((size_t)blockIdx.z * OC + o_g ) * N + n) =
                    packh(c0, c1);
                *reinterpret_cast<uint32_t*>(o16 + ((size_t)blockIdx.z * OC + o_g8) * N + n) =
                    packh(c2, c3);
            }
        }
    }
}

// fused Q/K/V projection with smem-staged coalesced epilogue for q/k.
__global__ void __launch_bounds__(256)
gemm_qkv(const __half* __restrict__ wts,
         const float* __restrict__ bq, const float* __restrict__ bk,
         const float* __restrict__ bv,
         const __half* __restrict__ xt, const __half* __restrict__ st,
         __half* __restrict__ qp, __half* __restrict__ kp,
         __half* __restrict__ vp, int N)
{
    extern __shared__ __half smh[];
    const int z = blockIdx.z;
    const int which = z >> 1;
    const int b = z & 1;
    const __half* W    = wts + which * 65536;
    const float* bias  = (which == 0) ? bq : (which == 1) ? bk : bv;
    const __half* X    = (which == 0) ? xt : st;
    const float oscale = (which == 0) ? QSCALE : 1.0f;

    GemmOut R;
    gemm_body_h(W, X, DD, DD, nullptr, DD, b, DD, N,
                blockIdx.y * 128, blockIdx.x * 128, smh, R);

    const int t = threadIdx.x;

    if (which < 2) {
        __half* St = smh;
        __syncthreads();
        #pragma unroll
        for (int mt = 0; mt < 4; mt++) {
            int ol  = R.wo + mt * 16 + R.g;
            int ol8 = ol + 8;
            float bg  = bias[R.o0 + ol];
            float bg8 = bias[R.o0 + ol8];
            int col  = (ol  & 3) * 32 + (ol  >> 2);
            int col8 = (ol8 & 3) * 32 + (ol8 >> 2);
            #pragma unroll
            for (int nt = 0; nt < 4; nt++) {
                int nl = R.wn + nt * 8 + 2 * R.tg;
                St[(nl    ) * 136 + col ] = __float2half_rn((R.acc[mt][nt][0] + bg)  * oscale);
                St[(nl + 1) * 136 + col ] = __float2half_rn((R.acc[mt][nt][1] + bg)  * oscale);
                St[(nl    ) * 136 + col8] = __float2half_rn((R.acc[mt][nt][2] + bg8) * oscale);
                St[(nl + 1) * 136 + col8] = __float2half_rn((R.acc[mt][nt][3] + bg8) * oscale);
            }
        }
        __syncthreads();

        __half* out = (which == 0) ? qp : kp;
        const int di0 = R.o0 >> 2;
        #pragma unroll
        for (int it = 0; it < 8; it++) {
            int idx = t + it * 256;
            int quad = idx & 3, pr = idx >> 2;
            int hh = pr >> 7, nl = pr & 127;
            uint4 val = *reinterpret_cast<const uint4*>(St + nl * 136 + hh * 32 + quad * 8);
            *reinterpret_cast<uint4*>(
                out + (((size_t)b * HH + hh) * N + R.n0 + nl) * 64 + di0 + quad * 8) = val;
        }
    } else {
        #pragma unroll
        for (int mt = 0; mt < 4; mt++) {
            int o_g  = R.o0 + R.wo + mt * 16 + R.g;
            int o_g8 = o_g + 8;
            float bg  = bias[o_g];
            float bg8 = bias[o_g8];
            #pragma unroll
            for (int nt = 0; nt < 4; nt++) {
                int n = R.n0 + R.wn + nt * 8 + 2 * R.tg;
                int h0 = o_g & 3,  d0 = o_g >> 2;
                int h1 = o_g8 & 3, d1 = o_g8 >> 2;
                *reinterpret_cast<uint32_t*>(
                    vp + (((size_t)b * HH + h0) * 64 + d0) * N + n) =
                    packh(R.acc[mt][nt][0] + bg, R.acc[mt][nt][1] + bg);
                *reinterpret_cast<uint32_t*>(
                    vp + (((size_t)b * HH + h1) * 64 + d1) * N + n) =
                    packh(R.acc[mt][nt][2] + bg8, R.acc[mt][nt][3] + bg8);
            }
        }
    }
}

// ---------------------------------------------------------------------------
// InstanceNorm stats + normalize/transpose
// ---------------------------------------------------------------------------
__global__ void inst_stats(const __half* __restrict__ hb, float* __restrict__ stats, int N)
{
    int row = blockIdx.x;
    const __half* p = hb + (size_t)row * N;

    float s = 0.f, s2 = 0.f;
    for (int i = threadIdx.x * 8; i < N; i += 256 * 8) {
        uint4 raw = *reinterpret_cast<const uint4*>(p + i);
        const __half2* h2 = reinterpret_cast<const __half2*>(&raw);
        #pragma unroll
        for (int kk = 0; kk < 4; kk++) {
            float2 f = __half22float2(h2[kk]);
            s  += f.x + f.y;
            s2 += f.x * f.x + f.y * f.y;
        }
    }
    #pragma unroll
    for (int off = 16; off > 0; off >>= 1) {
        s  += __shfl_xor_sync(0xffffffffu, s,  off);
        s2 += __shfl_xor_sync(0xffffffffu, s2, off);
    }
    __shared__ float sh[16];
    int wid = threadIdx.x >> 5, lid = threadIdx.x & 31;
    if (lid == 0) { sh[wid] = s; sh[wid + 8] = s2; }
    __syncthreads();
    if (threadIdx.x == 0) {
        s = 0.f; s2 = 0.f;
        #pragma unroll
        for (int w = 0; w < 8; w++) { s += sh[w]; s2 += sh[w + 8]; }
        float mean = s / (float)N;
        float var  = s2 / (float)N - mean * mean;
        stats[row * 2]     = mean;
        stats[row * 2 + 1] = rsqrtf(var + 1e-5f);
    }
}

__global__ void norm_transpose(const __half* __restrict__ hb, const float* __restrict__ stats,
                               __half* __restrict__ ht, int N)
{
    __shared__ __half tile[32][33];
    const int b = blockIdx.z;
    const int c0 = blockIdx.y * 32, n0 = blockIdx.x * 32;
    const int tx = threadIdx.x & 31, ty = threadIdx.x >> 5;

    #pragma unroll
    for (int i = 0; i < 4; i++) {
        int c = ty + i * 8;
        int row = b * 512 + c0 + c;
        float mu  = stats[row * 2];
        float inv = stats[row * 2 + 1];
        float v = __half2float(hb[(size_t)row * N + n0 + tx]);
        tile[c][tx] = __float2half_rn(fmaxf(0.f, (v - mu) * inv));
    }
    __syncthreads();
    #pragma unroll
    for (int i = 0; i < 4; i++) {
        int n = ty + i * 8;
        ht[((size_t)b * N + n0 + n) * 512 + c0 + tx] = tile[tx][n];
    }
}

// ---------------------------------------------------------------------------
extern "C" void kernel_launch(void* const* d_in, const int* in_sizes, int n_in,
                              void* d_out, int out_size)
{
    const float* x   = (const float*)d_in[0];
    const float* src = (const float*)d_in[1];
    const float* Wq  = (const float*)d_in[2];
    const float* bq  = (const float*)d_in[3];
    const float* Wk  = (const float*)d_in[4];
    const float* bk  = (const float*)d_in[5];
    const float* Wv  = (const float*)d_in[6];
    const float* bv  = (const float*)d_in[7];
    const float* Wm  = (const float*)d_in[8];
    const float* bm  = (const float*)d_in[9];
    const float* W1  = (const float*)d_in[10];
    const float* b1  = (const float*)d_in[11];
    const float* W2  = (const float*)d_in[12];
    const float* b2  = (const float*)d_in[13];

    const int B = BB, D = DD;
    const int N = in_sizes[0] / (B * D);
    const int M = in_sizes[1] / (B * D);

    __half *qp, *kp, *vp, *xtp, *stp, *attnp, *hp, *htp, *wts, *wcat;
    float *bf, *stats;
    cudaGetSymbolAddress((void**)&qp,    g_q);
    cudaGetSymbolAddress((void**)&kp,    g_k);
    cudaGetSymbolAddress((void**)&vp,    g_v);
    cudaGetSymbolAddress((void**)&xtp,   g_xt);
    cudaGetSymbolAddress((void**)&stp,   g_st);
    cudaGetSymbolAddress((void**)&attnp, g_attn);
    cudaGetSymbolAddress((void**)&hp,    g_h);
    cudaGetSymbolAddress((void**)&htp,   g_ht);
    cudaGetSymbolAddress((void**)&wts,   g_wts);
    cudaGetSymbolAddress((void**)&wcat,  g_wcat);
    cudaGetSymbolAddress((void**)&bf,    g_bf);
    cudaGetSymbolAddress((void**)&stats, g_stats);

    const int gsmem = 4 * 128 * LDH2 * (int)sizeof(__half);  // 73728
    const int fsmem = 18432 + 20736 + 18432;                  // 57600
    cudaFuncSetAttribute(gemm_h,   cudaFuncAttributeMaxDynamicSharedMemorySize, gsmem);
    cudaFuncSetAttribute(gemm_qkv, cudaFuncAttributeMaxDynamicSharedMemorySize, gsmem);
    cudaFuncSetAttribute(flash_attn_fp16, cudaFuncAttributeMaxDynamicSharedMemorySize, fsmem);

    // 0. fused producers (weights fp16 + input transpose + W1 fold)
    const int nProd = 2560 + (N / 32) * 8 * 4 + 512;
    producers<<<nProd, 256>>>(Wq, Wk, Wv, Wm, W1, W2, wts,
                              x, src, xtp, stp, b1, bm, wcat, bf, N);

    // 1. fused Q/K/V projections
    gemm_qkv<<<dim3(N / 128, D / 128, 3 * B), 256, gsmem>>>(
        wts, bq, bk, bv, xtp, stp, qp, kp, vp, N);

    // 2. fp16 flash attention -> attn_t (B,N,256)
    flash_attn_fp16<<<dim3(N / 128, HH, B), 128, fsmem>>>(qp, kp, vp, attnp, N, M);

    // 3. fused W1 layer -> h (B,2D,N) fp16
    gemm_h<<<dim3(N / 128, (2 * D) / 128, B), 256, gsmem>>>(
        wcat, bf, xtp, D, D, attnp, D, hp, 2 * D, 2 * D, N, 1);

    // 4. InstanceNorm stats + normalize/transpose -> ht (B,N,512)
    inst_stats<<<B * 2 * D, 256>>>(hp, stats, N);
    norm_transpose<<<dim3(N / 32, (2 * D) / 32, B), 256>>>(hp, stats, htp, N);

    // 5. final projection -> d_out (B,D,N) fp32
    gemm_h<<<dim3(N / 128, D / 128, B), 256, gsmem>>>(
        wts + OFF_W2, b2, htp, 2 * D, 2 * D, nullptr, 2 * D, d_out, D, 2 * D, N, 0);
}

// round 16
// speedup vs baseline: 1.1522x; 1.0208x over previous
#include <cuda_runtime.h>
#include <cuda_fp16.h>
#include <cstdint>
#include <cstddef>

// ---------------------------------------------------------------------------
// AttentionalPropagation, B=2, D=256, H=4, dim=64, N=M=4096.
// R16: R15 + __launch_bounds__(256,2) on GEMMs (cap regs 132->128, restoring
//      2 CTA/SM residency lost to BK=64's register growth).
// ---------------------------------------------------------------------------

#define BB 2
#define DD 256
#define HH 4

__device__ __half g_q[BB * HH * 4096 * 64];   // [b][h][n][di], pre-scaled
__device__ __half g_k[BB * HH * 4096 * 64];   // [b][h][m][di]
__device__ __half g_v[BB * HH * 64 * 4096];   // [b][h][di][m] (transposed)
__device__ __half g_xt  [BB * 4096 * DD];     // x  transposed (B,N,256) fp16
__device__ __half g_st  [BB * 4096 * DD];     // src transposed
__device__ __half g_attn[BB * 4096 * DD];     // attn (B,N,256), ch = h*64+di
__device__ __half g_h   [BB * 2 * DD * 4096]; // (B,2D,N) fp16 (pre-norm)
__device__ __half g_ht  [BB * 4096 * 2 * DD]; // (B,N,512) fp16 (post-norm)
__device__ __half g_wts [655360];             // fp16 weights
__device__ __half g_wcat[512 * 512];          // [W1x | perm(W1m@Wm)] fp16
__device__ float  g_bf  [512];                // W1m@bm + b1
__device__ float  g_stats[BB * 2 * DD * 2];   // per (b,c): mean, inv

#define OFF_WQ 0
#define OFF_WK 65536
#define OFF_WV 131072
#define OFF_WM 196608
#define OFF_W1 262144
#define OFF_W2 524288

#define QSCALE (0.125f * 1.44269504088896340736f)

// ============================ PTX helpers ==================================
__device__ __forceinline__ uint32_t smem_u32(const void* p) {
    uint32_t a;
    asm("{ .reg .u64 t; cvta.to.shared.u64 t, %1; cvt.u32.u64 %0, t; }"
        : "=r"(a) : "l"(p));
    return a;
}
__device__ __forceinline__ uint32_t packh(float lo, float hi) {
    __half2 h = __floats2half2_rn(lo, hi);
    return *reinterpret_cast<uint32_t*>(&h);
}
__device__ __forceinline__ uint32_t ex2h2(uint32_t h2) {
    uint32_t r; asm("ex2.approx.f16x2 %0, %1;" : "=r"(r) : "r"(h2)); return r;
}
__device__ __forceinline__ void mma16f(float* d, const uint32_t* a,
                                       uint32_t b0, uint32_t b1) {
    asm volatile("mma.sync.aligned.m16n8k16.row.col.f32.f16.f16.f32 "
        "{%0,%1,%2,%3}, {%4,%5,%6,%7}, {%8,%9}, {%0,%1,%2,%3};"
        : "+f"(d[0]), "+f"(d[1]), "+f"(d[2]), "+f"(d[3])
        : "r"(a[0]), "r"(a[1]), "r"(a[2]), "r"(a[3]), "r"(b0), "r"(b1));
}
__device__ __forceinline__ void ldsm4(uint32_t* r, uint32_t addr) {
    asm volatile("ldmatrix.sync.aligned.m8n8.x4.shared.b16 {%0,%1,%2,%3}, [%4];"
        : "=r"(r[0]), "=r"(r[1]), "=r"(r[2]), "=r"(r[3]) : "r"(addr));
}
__device__ __forceinline__ void cp16(uint32_t s, const void* g) {
    asm volatile("cp.async.ca.shared.global [%0], [%1], 16;" :: "r"(s), "l"(g));
}
#define CP_COMMIT() asm volatile("cp.async.commit_group;" ::: "memory")
#define CP_WAIT(n)  asm volatile("cp.async.wait_group %0;" :: "n"(n) : "memory")

// ---------------------------------------------------------------------------
// Fused producers: weight fp16 conversion + input transpose + W1 fold.
// ---------------------------------------------------------------------------
__global__ void producers(const float* __restrict__ wq, const float* __restrict__ wk,
                          const float* __restrict__ wv, const float* __restrict__ wm,
                          const float* __restrict__ w1, const float* __restrict__ w2,
                          __half* __restrict__ wts,
                          const float* __restrict__ x, const float* __restrict__ src,
                          __half* __restrict__ xt, __half* __restrict__ st,
                          const float* __restrict__ b1, const float* __restrict__ bm,
                          __half* __restrict__ wcat, float* __restrict__ bf, int N)
{
    __shared__ __half tile[32][33];
    const int bx = blockIdx.x;
    const int nWB = 2560;
    const int nx  = N / 32;
    const int nTB = nx * 8 * 4;

    if (bx < nWB) {
        int i = bx * 256 + threadIdx.x;
        float v;
        if      (i < OFF_WK) v = wq[i - OFF_WQ];
        else if (i < OFF_WV) v = wk[i - OFF_WK];
        else if (i < OFF_WM) v = wv[i - OFF_WV];
        else if (i < OFF_W1) v = wm[i - OFF_WM];
        else if (i < OFF_W2) v = w1[i - OFF_W1];
        else                 v = w2[i - OFF_W2];
        wts[i] = __float2half_rn(v);
    } else if (bx < nWB + nTB) {
        int f = bx - nWB;
        int cx = f % nx;
        int rest = f / nx;
        int cy = rest & 7;
        int zz = rest >> 3;
        const int which = zz >> 1, b = zz & 1;
        const float* in = which ? src : x;
        __half* out = which ? st : xt;
        const int c0 = cy * 32, n0 = cx * 32;
        const int tx = threadIdx.x & 31, ty = threadIdx.x >> 5;

        #pragma unroll
        for (int i = 0; i < 4; i++) {
            int c = ty + i * 8;
            tile[c][tx] = __float2half_rn(in[((size_t)(b * DD + c0 + c)) * N + n0 + tx]);
        }
        __syncthreads();
        #pragma unroll
        for (int i = 0; i < 4; i++) {
            int n = ty + i * 8;
            out[((size_t)b * N + n0 + n) * DD + c0 + tx] = tile[tx][n];
        }
    } else {
        int o = bx - nWB - nTB;
        int j = threadIdx.x;

        wcat[o * 512 + j] = __float2half_rn(w1[o * 512 + j]);

        float acc = 0.f;
        const float* w1m = w1 + o * 512 + 256;
        #pragma unroll 8
        for (int kk = 0; kk < 256; kk++)
            acc = fmaf(w1m[kk], wm[kk * 256 + j], acc);
        int jp = (j & 3) * 64 + (j >> 2);
        wcat[o * 512 + 256 + jp] = __float2half_rn(acc);

        if (j == 0) {
            float b = b1[o];
            for (int kk = 0; kk < 256; kk++) b = fmaf(w1m[kk], bm[kk], b);
            bf[o] = b;
        }
    }
}

// ---------------------------------------------------------------------------
// fp16 flash attention (R11 configuration, unchanged).
// ---------------------------------------------------------------------------
#define LDB   72
#define VROWS 72

__global__ void __launch_bounds__(128)
flash_attn_fp16(const __half* __restrict__ q, const __half* __restrict__ k,
                const __half* __restrict__ v, __half* __restrict__ attn,
                int N, int M)
{
    extern __shared__ char smb[];
    __half* Ks = reinterpret_cast<__half*>(smb);             // [2][64][LDB]
    __half* Vs = reinterpret_cast<__half*>(smb + 18432);     // [2][VROWS][LDB]
    __half* Qs = reinterpret_cast<__half*>(smb + 39168);     // [128][LDB]
    __half* OTh = reinterpret_cast<__half*>(smb);            // [128][72] epilogue

    const int b  = blockIdx.z, h = blockIdx.y;
    const int n0 = blockIdx.x * 128;
    const int bh = b * HH + h;
    const int t  = threadIdx.x;
    const int wid = t >> 5, lane = t & 31;
    const int g = lane >> 2, tg = lane & 3;
    const int wr = wid * 32;
    const int lrow = lane & 7;
    const int lcol = (lane >> 3) * 8;

    const __half* Kg = k + (size_t)bh * M * 64;
    const __half* Vg = v + (size_t)bh * 64 * M;

    {
        uint32_t kd = smem_u32(Ks), vd = smem_u32(Vs);
        #pragma unroll
        for (int i = 0; i < 4; i++) {
            int idx = t + i * 128;
            int r = idx >> 3, c = (idx & 7) * 8;
            cp16(kd + (uint32_t)(r * LDB + c) * 2, Kg + r * 64 + c);
            cp16(vd + (uint32_t)(r * LDB + c) * 2, Vg + (size_t)r * M + c);
        }
        CP_COMMIT();
    }

    {
        const __half one = __float2half(1.0f);
        const __half zer = __float2half(0.0f);
        for (int i = t; i < 2 * 8 * LDB; i += 128) {
            int buf = i / (8 * LDB);
            int rem = i - buf * 8 * LDB;
            int r = rem / LDB, c = rem - r * LDB;
            Vs[(size_t)buf * VROWS * LDB + (64 + r) * LDB + c] = (r == 0) ? one : zer;
        }
    }

    {
        const __half* Qg = q + ((size_t)bh * N + n0) * 64;
        #pragma unroll
        for (int i = 0; i < 8; i++) {
            int idx = t + i * 128;
            int r = idx >> 3, c = (idx & 7) * 8;
            *reinterpret_cast<uint4*>(Qs + r * LDB + c) =
                *reinterpret_cast<const uint4*>(Qg + r * 64 + c);
        }
    }
    __syncthreads();

    uint32_t Qf[2][4][4];
    #pragma unroll
    for (int mt = 0; mt < 2; mt++) {
        int r0 = wr + mt * 16 + g;
        #pragma unroll
        for (int kk = 0; kk < 4; kk++) {
            Qf[mt][kk][0] = *reinterpret_cast<uint32_t*>(Qs + (r0    ) * LDB + kk * 16 + 2 * tg);
            Qf[mt][kk][1] = *reinterpret_cast<uint32_t*>(Qs + (r0 + 8) * LDB + kk * 16 + 2 * tg);
            Qf[mt][kk][2] = *reinterpret_cast<uint32_t*>(Qs + (r0    ) * LDB + kk * 16 + 2 * tg + 8);
            Qf[mt][kk][3] = *reinterpret_cast<uint32_t*>(Qs + (r0 + 8) * LDB + kk * 16 + 2 * tg + 8);
        }
    }
    __syncthreads();

    float Of[9][2][4] = {};

    const int nT = M / 64;
    for (int tt = 0; tt < nT; tt++) {
        const __half* Kc = Ks + (size_t)(tt & 1) * 64 * LDB;
        const __half* Vc = Vs + (size_t)(tt & 1) * VROWS * LDB;

        if (tt + 1 < nT) {
            uint32_t kd = smem_u32(Ks + (size_t)((tt + 1) & 1) * 64 * LDB);
            uint32_t vd = smem_u32(Vs + (size_t)((tt + 1) & 1) * VROWS * LDB);
            const __half* Kn = Kg + (size_t)(tt + 1) * 64 * 64;
            const __half* Vn = Vg + (size_t)(tt + 1) * 64;
            #pragma unroll
            for (int i = 0; i < 4; i++) {
                int idx = t + i * 128;
                int r = idx >> 3, c = (idx & 7) * 8;
                cp16(kd + (uint32_t)(r * LDB + c) * 2, Kn + r * 64 + c);
                cp16(vd + (uint32_t)(r * LDB + c) * 2, Vn + (size_t)r * M + c);
            }
            CP_COMMIT();
            CP_WAIT(1);
        } else {
            CP_WAIT(0);
        }
        __syncthreads();

        const uint32_t kb = smem_u32(Kc);
        const uint32_t vb = smem_u32(Vc);

        float Sc[8][2][4] = {};
        #pragma unroll
        for (int jp = 0; jp < 4; jp++) {
            uint32_t Kf[2][8];
            #pragma unroll
            for (int jj = 0; jj < 2; jj++) {
                uint32_t a = kb + (uint32_t)(((jp * 2 + jj) * 8 + lrow) * LDB + lcol) * 2;
                ldsm4(Kf[jj],     a);
                ldsm4(Kf[jj] + 4, a + 64);
            }
            #pragma unroll
            for (int kk = 0; kk < 4; kk++) {
                mma16f(Sc[jp * 2    ][0], Qf[0][kk], Kf[0][kk * 2], Kf[0][kk * 2 + 1]);
                mma16f(Sc[jp * 2    ][1], Qf[1][kk], Kf[0][kk * 2], Kf[0][kk * 2 + 1]);
                mma16f(Sc[jp * 2 + 1][0], Qf[0][kk], Kf[1][kk * 2], Kf[1][kk * 2 + 1]);
                mma16f(Sc[jp * 2 + 1][1], Qf[1][kk], Kf[1][kk * 2], Kf[1][kk * 2 + 1]);
            }
        }

        uint32_t Pa[4][2][4];
        #pragma unroll
        for (int mt = 0; mt < 2; mt++) {
            #pragma unroll
            for (int j = 0; j < 8; j++) {
                int kk = j >> 1, hf = (j & 1) * 2;
                Pa[kk][mt][hf    ] = ex2h2(packh(Sc[j][mt][0], Sc[j][mt][1]));
                Pa[kk][mt][hf + 1] = ex2h2(packh(Sc[j][mt][2], Sc[j][mt][3]));
            }
        }

        #pragma unroll
        for (int jp = 0; jp < 4; jp++) {
            uint32_t Vf[2][8];
            #pragma unroll
            for (int jj = 0; jj < 2; jj++) {
                uint32_t a = vb + (uint32_t)(((jp * 2 + jj) * 8 + lrow) * LDB + lcol) * 2;
                ldsm4(Vf[jj],     a);
                ldsm4(Vf[jj] + 4, a + 64);
            }
            #pragma unroll
            for (int kk = 0; kk < 4; kk++) {
                mma16f(Of[jp * 2    ][0], Pa[kk][0], Vf[0][kk * 2], Vf[0][kk * 2 + 1]);
                mma16f(Of[jp * 2    ][1], Pa[kk][1], Vf[0][kk * 2], Vf[0][kk * 2 + 1]);
                mma16f(Of[jp * 2 + 1][0], Pa[kk][0], Vf[1][kk * 2], Vf[1][kk * 2 + 1]);
                mma16f(Of[jp * 2 + 1][1], Pa[kk][1], Vf[1][kk * 2], Vf[1][kk * 2 + 1]);
            }
        }
        {
            uint32_t Vf8[8];
            uint32_t a = vb + (uint32_t)((64 + lrow) * LDB + lcol) * 2;
            ldsm4(Vf8,     a);
            ldsm4(Vf8 + 4, a + 64);
            #pragma unroll
            for (int kk = 0; kk < 4; kk++) {
                mma16f(Of[8][0], Pa[kk][0], Vf8[kk * 2], Vf8[kk * 2 + 1]);
                mma16f(Of[8][1], Pa[kk][1], Vf8[kk * 2], Vf8[kk * 2 + 1]);
            }
        }
        __syncthreads();
    }

    float linv[2][2];
    #pragma unroll
    for (int mt = 0; mt < 2; mt++) {
        float l0 = __shfl_sync(0xffffffffu, Of[8][mt][0], lane & ~3);
        float l1 = __shfl_sync(0xffffffffu, Of[8][mt][2], lane & ~3);
        linv[mt][0] = 1.0f / l0;
        linv[mt][1] = 1.0f / l1;
    }

    __syncthreads();
    #pragma unroll
    for (int j = 0; j < 8; j++) {
        #pragma unroll
        for (int mt = 0; mt < 2; mt++) {
            int r0 = wr + mt * 16 + g;
            *reinterpret_cast<uint32_t*>(OTh + (r0    ) * 72 + j * 8 + 2 * tg) =
                packh(Of[j][mt][0] * linv[mt][0], Of[j][mt][1] * linv[mt][0]);
            *reinterpret_cast<uint32_t*>(OTh + (r0 + 8) * 72 + j * 8 + 2 * tg) =
                packh(Of[j][mt][2] * linv[mt][1], Of[j][mt][3] * linv[mt][1]);
        }
    }
    __syncthreads();

    __half* Ag = attn + ((size_t)b * N + n0) * DD + h * 64;
    #pragma unroll
    for (int it = 0; it < 8; it++) {
        int n = it * 16 + (t >> 3);
        int qd = (t & 7) * 8;
        uint4 val = *reinterpret_cast<const uint4*>(OTh + n * 72 + qd);
        *reinterpret_cast<uint4*>(Ag + (size_t)n * DD + qd) = val;
    }
}

// ---------------------------------------------------------------------------
// fp16 GEMM body, BK=64, ldmatrix fragment loads.
// Tile 128x128; 8 warps = 2(o) x 4(n), warp tile 64x32.
// ---------------------------------------------------------------------------
#define LDH2 72

struct GemmOut {
    float acc[4][4][4];
    int o0, n0, wo, wn, g, tg;
};

__device__ __forceinline__ void gemm_body_h(
    const __half* __restrict__ W, const __half* __restrict__ X0, int S0, int C0,
    const __half* __restrict__ X1, int S1, int b, int IC, int N,
    int o0, int n0, __half* sm, GemmOut& R)
{
    __half* Ws = sm;                    // [2][128][LDH2]
    __half* Xs = sm + 2 * 128 * LDH2;   // [2][128][LDH2]

    const int t  = threadIdx.x;
    const int wid = t >> 5, lane = t & 31;
    R.g = lane >> 2; R.tg = lane & 3;
    R.wo = (wid & 1) * 64;
    R.wn = (wid >> 1) * 32;
    R.o0 = o0; R.n0 = n0;
    const int a_row = (lane & 7) + ((lane >> 3) & 1) * 8;
    const int a_col = (lane >> 4) * 8;
    const int b_row = lane & 7;
    const int b_col = (lane >> 3) * 8;

    auto stage = [&](int buf, int k0) {
        uint32_t wd = smem_u32(Ws + buf * 128 * LDH2);
        uint32_t xd = smem_u32(Xs + buf * 128 * LDH2);
        #pragma unroll
        for (int i = 0; i < 4; i++) {
            int idx = t + i * 256;
            int r = idx >> 3, c = (idx & 7) * 8;
            cp16(wd + (uint32_t)(r * LDH2 + c) * 2, W + (size_t)(o0 + r) * IC + k0 + c);
        }
        const __half* xb; int S;
        if (k0 < C0) { xb = X0 + (size_t)b * N * S0 + k0;        S = S0; }
        else         { xb = X1 + (size_t)b * N * S1 + (k0 - C0); S = S1; }
        #pragma unroll
        for (int i = 0; i < 4; i++) {
            int idx = t + i * 256;
            int r = idx >> 3, c = (idx & 7) * 8;
            cp16(xd + (uint32_t)(r * LDH2 + c) * 2, xb + (size_t)(n0 + r) * S + c);
        }
        CP_COMMIT();
    };

    stage(0, 0);
    #pragma unroll
    for (int a = 0; a < 4; a++)
        #pragma unroll
        for (int c = 0; c < 4; c++)
            #pragma unroll
            for (int d = 0; d < 4; d++) R.acc[a][c][d] = 0.f;

    const int nK = IC / 64;
    for (int kt = 0; kt < nK; kt++) {
        if (kt + 1 < nK) { stage((kt + 1) & 1, (kt + 1) * 64); CP_WAIT(1); }
        else             { CP_WAIT(0); }
        __syncthreads();
        const uint32_t wb = smem_u32(Ws + (kt & 1) * 128 * LDH2);
        const uint32_t xb = smem_u32(Xs + (kt & 1) * 128 * LDH2);

        #pragma unroll
        for (int h2 = 0; h2 < 2; h2++) {
            uint32_t Bf[4][4];
            #pragma unroll
            for (int nt = 0; nt < 4; nt++)
                ldsm4(Bf[nt], xb + (uint32_t)((R.wn + nt * 8 + b_row) * LDH2
                                              + h2 * 32 + b_col) * 2);
            #pragma unroll
            for (int ks = 0; ks < 2; ks++) {
                uint32_t Af[4][4];
                #pragma unroll
                for (int mt = 0; mt < 4; mt++)
                    ldsm4(Af[mt], wb + (uint32_t)((R.wo + mt * 16 + a_row) * LDH2
                                                  + h2 * 32 + ks * 16 + a_col) * 2);
                #pragma unroll
                for (int nt = 0; nt < 4; nt++)
                    #pragma unroll
                    for (int mt = 0; mt < 4; mt++)
                        mma16f(R.acc[mt][nt], Af[mt], Bf[nt][ks * 2], Bf[nt][ks * 2 + 1]);
            }
        }
        __syncthreads();
    }
}

// generic projection. mode 0: fp32 (B,OC,N); mode 1: fp16 (B,OC,N).
__global__ void __launch_bounds__(256, 2)
gemm_h(const __half* __restrict__ W, const float* __restrict__ bias,
       const __half* __restrict__ X0, int S0, int C0,
       const __half* __restrict__ X1, int S1,
       void* __restrict__ out, int OC, int IC, int N, int mode)
{
    extern __shared__ __half smh[];
    GemmOut R;
    gemm_body_h(W, X0, S0, C0, X1, S1, blockIdx.z, IC, N,
                blockIdx.y * 128, blockIdx.x * 128, smh, R);

    #pragma unroll
    for (int mt = 0; mt < 4; mt++) {
        int o_g  = R.o0 + R.wo + mt * 16 + R.g;
        int o_g8 = o_g + 8;
        float bg  = bias[o_g];
        float bg8 = bias[o_g8];
        #pragma unroll
        for (int nt = 0; nt < 4; nt++) {
            int n = R.n0 + R.wn + nt * 8 + 2 * R.tg;
            float c0 = R.acc[mt][nt][0] + bg,  c1 = R.acc[mt][nt][1] + bg;
            float c2 = R.acc[mt][nt][2] + bg8, c3 = R.acc[mt][nt][3] + bg8;
            if (mode == 0) {
                float* o32 = (float*)out;
                *reinterpret_cast<float2*>(o32 + ((size_t)blockIdx.z * OC + o_g ) * N + n) =
                    make_float2(c0, c1);
                *reinterpret_cast<float2*>(o32 + ((size_t)blockIdx.z * OC + o_g8) * N + n) =
                    make_float2(c2, c3);
            } else {
                __half* o16 = (__half*)out;
                *reinterpret_cast<uint32_t*>(o16 + ((size_t)blockIdx.z * OC + o_g ) * N + n) =
                    packh(c0, c1);
                *reinterpret_cast<uint32_t*>(o16 + ((size_t)blockIdx.z * OC + o_g8) * N + n) =
                    packh(c2, c3);
            }
        }
    }
}

// fused Q/K/V projection with smem-staged coalesced epilogue for q/k.
__global__ void __launch_bounds__(256, 2)
gemm_qkv(const __half* __restrict__ wts,
         const float* __restrict__ bq, const float* __restrict__ bk,
         const float* __restrict__ bv,
         const __half* __restrict__ xt, const __half* __restrict__ st,
         __half* __restrict__ qp, __half* __restrict__ kp,
         __half* __restrict__ vp, int N)
{
    extern __shared__ __half smh[];
    const int z = blockIdx.z;
    const int which = z >> 1;
    const int b = z & 1;
    const __half* W    = wts + which * 65536;
    const float* bias  = (which == 0) ? bq : (which == 1) ? bk : bv;
    const __half* X    = (which == 0) ? xt : st;
    const float oscale = (which == 0) ? QSCALE : 1.0f;

    GemmOut R;
    gemm_body_h(W, X, DD, DD, nullptr, DD, b, DD, N,
                blockIdx.y * 128, blockIdx.x * 128, smh, R);

    const int t = threadIdx.x;

    if (which < 2) {
        __half* St = smh;
        __syncthreads();
        #pragma unroll
        for (int mt = 0; mt < 4; mt++) {
            int ol  = R.wo + mt * 16 + R.g;
            int ol8 = ol + 8;
            float bg  = bias[R.o0 + ol];
            float bg8 = bias[R.o0 + ol8];
            int col  = (ol  & 3) * 32 + (ol  >> 2);
            int col8 = (ol8 & 3) * 32 + (ol8 >> 2);
            #pragma unroll
            for (int nt = 0; nt < 4; nt++) {
                int nl = R.wn + nt * 8 + 2 * R.tg;
                St[(nl    ) * 136 + col ] = __float2half_rn((R.acc[mt][nt][0] + bg)  * oscale);
                St[(nl + 1) * 136 + col ] = __float2half_rn((R.acc[mt][nt][1] + bg)  * oscale);
                St[(nl    ) * 136 + col8] = __float2half_rn((R.acc[mt][nt][2] + bg8) * oscale);
                St[(nl + 1) * 136 + col8] = __float2half_rn((R.acc[mt][nt][3] + bg8) * oscale);
            }
        }
        __syncthreads();

        __half* out = (which == 0) ? qp : kp;
        const int di0 = R.o0 >> 2;
        #pragma unroll
        for (int it = 0; it < 8; it++) {
            int idx = t + it * 256;
            int quad = idx & 3, pr = idx >> 2;
            int hh = pr >> 7, nl = pr & 127;
            uint4 val = *reinterpret_cast<const uint4*>(St + nl * 136 + hh * 32 + quad * 8);
            *reinterpret_cast<uint4*>(
                out + (((size_t)b * HH + hh) * N + R.n0 + nl) * 64 + di0 + quad * 8) = val;
        }
    } else {
        #pragma unroll
        for (int mt = 0; mt < 4; mt++) {
            int o_g  = R.o0 + R.wo + mt * 16 + R.g;
            int o_g8 = o_g + 8;
            float bg  = bias[o_g];
            float bg8 = bias[o_g8];
            #pragma unroll
            for (int nt = 0; nt < 4; nt++) {
                int n = R.n0 + R.wn + nt * 8 + 2 * R.tg;
                int h0 = o_g & 3,  d0 = o_g >> 2;
                int h1 = o_g8 & 3, d1 = o_g8 >> 2;
                *reinterpret_cast<uint32_t*>(
                    vp + (((size_t)b * HH + h0) * 64 + d0) * N + n) =
                    packh(R.acc[mt][nt][0] + bg, R.acc[mt][nt][1] + bg);
                *reinterpret_cast<uint32_t*>(
                    vp + (((size_t)b * HH + h1) * 64 + d1) * N + n) =
                    packh(R.acc[mt][nt][2] + bg8, R.acc[mt][nt][3] + bg8);
            }
        }
    }
}

// ---------------------------------------------------------------------------
// InstanceNorm stats + normalize/transpose
// ---------------------------------------------------------------------------
__global__ void inst_stats(const __half* __restrict__ hb, float* __restrict__ stats, int N)
{
    int row = blockIdx.x;
    const __half* p = hb + (size_t)row * N;

    float s = 0.f, s2 = 0.f;
    for (int i = threadIdx.x * 8; i < N; i += 256 * 8) {
        uint4 raw = *reinterpret_cast<const uint4*>(p + i);
        const __half2* h2 = reinterpret_cast<const __half2*>(&raw);
        #pragma unroll
        for (int kk = 0; kk < 4; kk++) {
            float2 f = __half22float2(h2[kk]);
            s  += f.x + f.y;
            s2 += f.x * f.x + f.y * f.y;
        }
    }
    #pragma unroll
    for (int off = 16; off > 0; off >>= 1) {
        s  += __shfl_xor_sync(0xffffffffu, s,  off);
        s2 += __shfl_xor_sync(0xffffffffu, s2, off);
    }
    __shared__ float sh[16];
    int wid = threadIdx.x >> 5, lid = threadIdx.x & 31;
    if (lid == 0) { sh[wid] = s; sh[wid + 8] = s2; }
    __syncthreads();
    if (threadIdx.x == 0) {
        s = 0.f; s2 = 0.f;
        #pragma unroll
        for (int w = 0; w < 8; w++) { s += sh[w]; s2 += sh[w + 8]; }
        float mean = s / (float)N;
        float var  = s2 / (float)N - mean * mean;
        stats[row * 2]     = mean;
        stats[row * 2 + 1] = rsqrtf(var + 1e-5f);
    }
}

__global__ void norm_transpose(const __half* __restrict__ hb, const float* __restrict__ stats,
                               __half* __restrict__ ht, int N)
{
    __shared__ __half tile[32][33];
    const int b = blockIdx.z;
    const int c0 = blockIdx.y * 32, n0 = blockIdx.x * 32;
    const int tx = threadIdx.x & 31, ty = threadIdx.x >> 5;

    #pragma unroll
    for (int i = 0; i < 4; i++) {
        int c = ty + i * 8;
        int row = b * 512 + c0 + c;
        float mu  = stats[row * 2];
        float inv = stats[row * 2 + 1];
        float v = __half2float(hb[(size_t)row * N + n0 + tx]);
        tile[c][tx] = __float2half_rn(fmaxf(0.f, (v - mu) * inv));
    }
    __syncthreads();
    #pragma unroll
    for (int i = 0; i < 4; i++) {
        int n = ty + i * 8;
        ht[((size_t)b * N + n0 + n) * 512 + c0 + tx] = tile[tx][n];
    }
}

// ---------------------------------------------------------------------------
extern "C" void kernel_launch(void* const* d_in, const int* in_sizes, int n_in,
                              void* d_out, int out_size)
{
    const float* x   = (const float*)d_in[0];
    const float* src = (const float*)d_in[1];
    const float* Wq  = (const float*)d_in[2];
    const float* bq  = (const float*)d_in[3];
    const float* Wk  = (const float*)d_in[4];
    const float* bk  = (const float*)d_in[5];
    const float* Wv  = (const float*)d_in[6];
    const float* bv  = (const float*)d_in[7];
    const float* Wm  = (const float*)d_in[8];
    const float* bm  = (const float*)d_in[9];
    const float* W1  = (const float*)d_in[10];
    const float* b1  = (const float*)d_in[11];
    const float* W2  = (const float*)d_in[12];
    const float* b2  = (const float*)d_in[13];

    const int B = BB, D = DD;
    const int N = in_sizes[0] / (B * D);
    const int M = in_sizes[1] / (B * D);

    __half *qp, *kp, *vp, *xtp, *stp, *attnp, *hp, *htp, *wts, *wcat;
    float *bf, *stats;
    cudaGetSymbolAddress((void**)&qp,    g_q);
    cudaGetSymbolAddress((void**)&kp,    g_k);
    cudaGetSymbolAddress((void**)&vp,    g_v);
    cudaGetSymbolAddress((void**)&xtp,   g_xt);
    cudaGetSymbolAddress((void**)&stp,   g_st);
    cudaGetSymbolAddress((void**)&attnp, g_attn);
    cudaGetSymbolAddress((void**)&hp,    g_h);
    cudaGetSymbolAddress((void**)&htp,   g_ht);
    cudaGetSymbolAddress((void**)&wts,   g_wts);
    cudaGetSymbolAddress((void**)&wcat,  g_wcat);
    cudaGetSymbolAddress((void**)&bf,    g_bf);
    cudaGetSymbolAddress((void**)&stats, g_stats);

    const int gsmem = 4 * 128 * LDH2 * (int)sizeof(__half);  // 73728
    const int fsmem = 18432 + 20736 + 18432;                  // 57600
    cudaFuncSetAttribute(gemm_h,   cudaFuncAttributeMaxDynamicSharedMemorySize, gsmem);
    cudaFuncSetAttribute(gemm_qkv, cudaFuncAttributeMaxDynamicSharedMemorySize, gsmem);
    cudaFuncSetAttribute(flash_attn_fp16, cudaFuncAttributeMaxDynamicSharedMemorySize, fsmem);

    // 0. fused producers (weights fp16 + input transpose + W1 fold)
    const int nProd = 2560 + (N / 32) * 8 * 4 + 512;
    producers<<<nProd, 256>>>(Wq, Wk, Wv, Wm, W1, W2, wts,
                              x, src, xtp, stp, b1, bm, wcat, bf, N);

    // 1. fused Q/K/V projections
    gemm_qkv<<<dim3(N / 128, D / 128, 3 * B), 256, gsmem>>>(
        wts, bq, bk, bv, xtp, stp, qp, kp, vp, N);

    // 2. fp16 flash attention -> attn_t (B,N,256)
    flash_attn_fp16<<<dim3(N / 128, HH, B), 128, fsmem>>>(qp, kp, vp, attnp, N, M);

    // 3. fused W1 layer -> h (B,2D,N) fp16
    gemm_h<<<dim3(N / 128, (2 * D) / 128, B), 256, gsmem>>>(
        wcat, bf, xtp, D, D, attnp, D, hp, 2 * D, 2 * D, N, 1);

    // 4. InstanceNorm stats + normalize/transpose -> ht (B,N,512)
    inst_stats<<<B * 2 * D, 256>>>(hp, stats, N);
    norm_transpose<<<dim3(N / 32, (2 * D) / 32, B), 256>>>(hp, stats, htp, N);

    // 5. final projection -> d_out (B,D,N) fp32
    gemm_h<<<dim3(N / 128, D / 128, B), 256, gsmem>>>(
        wts + OFF_W2, b2, htp, 2 * D, 2 * D, nullptr, 2 * D, d_out, D, 2 * D, N, 0);
}

// round 17
// speedup vs baseline: 1.1551x; 1.0025x over previous
#include <cuda_runtime.h>
#include <cuda_fp16.h>
#include <cstdint>
#include <cstddef>

// ---------------------------------------------------------------------------
// AttentionalPropagation, B=2, D=256, H=4, dim=64, N=M=4096.
// R17: R16 + 3-stage cp.async pipelines (GEMM and flash) with a single
//      __syncthreads per iteration (WAR-safe by 3-buffer rotation).
// ---------------------------------------------------------------------------

#define BB 2
#define DD 256
#define HH 4

__device__ __half g_q[BB * HH * 4096 * 64];   // [b][h][n][di], pre-scaled
__device__ __half g_k[BB * HH * 4096 * 64];   // [b][h][m][di]
__device__ __half g_v[BB * HH * 64 * 4096];   // [b][h][di][m] (transposed)
__device__ __half g_xt  [BB * 4096 * DD];     // x  transposed (B,N,256) fp16
__device__ __half g_st  [BB * 4096 * DD];     // src transposed
__device__ __half g_attn[BB * 4096 * DD];     // attn (B,N,256), ch = h*64+di
__device__ __half g_h   [BB * 2 * DD * 4096]; // (B,2D,N) fp16 (pre-norm)
__device__ __half g_ht  [BB * 4096 * 2 * DD]; // (B,N,512) fp16 (post-norm)
__device__ __half g_wts [655360];             // fp16 weights
__device__ __half g_wcat[512 * 512];          // [W1x | perm(W1m@Wm)] fp16
__device__ float  g_bf  [512];                // W1m@bm + b1
__device__ float  g_stats[BB * 2 * DD * 2];   // per (b,c): mean, inv

#define OFF_WQ 0
#define OFF_WK 65536
#define OFF_WV 131072
#define OFF_WM 196608
#define OFF_W1 262144
#define OFF_W2 524288

#define QSCALE (0.125f * 1.44269504088896340736f)

// ============================ PTX helpers ==================================
__device__ __forceinline__ uint32_t smem_u32(const void* p) {
    uint32_t a;
    asm("{ .reg .u64 t; cvta.to.shared.u64 t, %1; cvt.u32.u64 %0, t; }"
        : "=r"(a) : "l"(p));
    return a;
}
__device__ __forceinline__ uint32_t packh(float lo, float hi) {
    __half2 h = __floats2half2_rn(lo, hi);
    return *reinterpret_cast<uint32_t*>(&h);
}
__device__ __forceinline__ uint32_t ex2h2(uint32_t h2) {
    uint32_t r; asm("ex2.approx.f16x2 %0, %1;" : "=r"(r) : "r"(h2)); return r;
}
__device__ __forceinline__ void mma16f(float* d, const uint32_t* a,
                                       uint32_t b0, uint32_t b1) {
    asm volatile("mma.sync.aligned.m16n8k16.row.col.f32.f16.f16.f32 "
        "{%0,%1,%2,%3}, {%4,%5,%6,%7}, {%8,%9}, {%0,%1,%2,%3};"
        : "+f"(d[0]), "+f"(d[1]), "+f"(d[2]), "+f"(d[3])
        : "r"(a[0]), "r"(a[1]), "r"(a[2]), "r"(a[3]), "r"(b0), "r"(b1));
}
__device__ __forceinline__ void ldsm4(uint32_t* r, uint32_t addr) {
    asm volatile("ldmatrix.sync.aligned.m8n8.x4.shared.b16 {%0,%1,%2,%3}, [%4];"
        : "=r"(r[0]), "=r"(r[1]), "=r"(r[2]), "=r"(r[3]) : "r"(addr));
}
__device__ __forceinline__ void cp16(uint32_t s, const void* g) {
    asm volatile("cp.async.ca.shared.global [%0], [%1], 16;" :: "r"(s), "l"(g));
}
#define CP_COMMIT() asm volatile("cp.async.commit_group;" ::: "memory")
#define CP_WAIT(n)  asm volatile("cp.async.wait_group %0;" :: "n"(n) : "memory")

// ---------------------------------------------------------------------------
// Fused producers: weight fp16 conversion + input transpose + W1 fold.
// ---------------------------------------------------------------------------
__global__ void producers(const float* __restrict__ wq, const float* __restrict__ wk,
                          const float* __restrict__ wv, const float* __restrict__ wm,
                          const float* __restrict__ w1, const float* __restrict__ w2,
                          __half* __restrict__ wts,
                          const float* __restrict__ x, const float* __restrict__ src,
                          __half* __restrict__ xt, __half* __restrict__ st,
                          const float* __restrict__ b1, const float* __restrict__ bm,
                          __half* __restrict__ wcat, float* __restrict__ bf, int N)
{
    __shared__ __half tile[32][33];
    const int bx = blockIdx.x;
    const int nWB = 2560;
    const int nx  = N / 32;
    const int nTB = nx * 8 * 4;

    if (bx < nWB) {
        int i = bx * 256 + threadIdx.x;
        float v;
        if      (i < OFF_WK) v = wq[i - OFF_WQ];
        else if (i < OFF_WV) v = wk[i - OFF_WK];
        else if (i < OFF_WM) v = wv[i - OFF_WV];
        else if (i < OFF_W1) v = wm[i - OFF_WM];
        else if (i < OFF_W2) v = w1[i - OFF_W1];
        else                 v = w2[i - OFF_W2];
        wts[i] = __float2half_rn(v);
    } else if (bx < nWB + nTB) {
        int f = bx - nWB;
        int cx = f % nx;
        int rest = f / nx;
        int cy = rest & 7;
        int zz = rest >> 3;
        const int which = zz >> 1, b = zz & 1;
        const float* in = which ? src : x;
        __half* out = which ? st : xt;
        const int c0 = cy * 32, n0 = cx * 32;
        const int tx = threadIdx.x & 31, ty = threadIdx.x >> 5;

        #pragma unroll
        for (int i = 0; i < 4; i++) {
            int c = ty + i * 8;
            tile[c][tx] = __float2half_rn(in[((size_t)(b * DD + c0 + c)) * N + n0 + tx]);
        }
        __syncthreads();
        #pragma unroll
        for (int i = 0; i < 4; i++) {
            int n = ty + i * 8;
            out[((size_t)b * N + n0 + n) * DD + c0 + tx] = tile[tx][n];
        }
    } else {
        int o = bx - nWB - nTB;
        int j = threadIdx.x;

        wcat[o * 512 + j] = __float2half_rn(w1[o * 512 + j]);

        float acc = 0.f;
        const float* w1m = w1 + o * 512 + 256;
        #pragma unroll 8
        for (int kk = 0; kk < 256; kk++)
            acc = fmaf(w1m[kk], wm[kk * 256 + j], acc);
        int jp = (j & 3) * 64 + (j >> 2);
        wcat[o * 512 + 256 + jp] = __float2half_rn(acc);

        if (j == 0) {
            float b = b1[o];
            for (int kk = 0; kk < 256; kk++) b = fmaf(w1m[kk], bm[kk], b);
            bf[o] = b;
        }
    }
}

// ---------------------------------------------------------------------------
// fp16 flash attention, 3-stage K/V pipeline, one sync per tile.
// 4 warps x 32 q-rows; ldmatrix; ex2.f16x2 softmax; tensor row-sum.
// grid (N/128, H, B), 128 threads.
// smem: Ks[3][64][72] 27648 | Vs[3][72][72] 31104 | Qs[128][72] 18432 = 77184
// ---------------------------------------------------------------------------
#define LDB   72
#define VROWS 72

__global__ void __launch_bounds__(128)
flash_attn_fp16(const __half* __restrict__ q, const __half* __restrict__ k,
                const __half* __restrict__ v, __half* __restrict__ attn,
                int N, int M)
{
    extern __shared__ char smb[];
    __half* Ks = reinterpret_cast<__half*>(smb);             // [3][64][LDB]
    __half* Vs = reinterpret_cast<__half*>(smb + 27648);     // [3][VROWS][LDB]
    __half* Qs = reinterpret_cast<__half*>(smb + 58752);     // [128][LDB]
    __half* OTh = reinterpret_cast<__half*>(smb);            // [128][72] epilogue

    const int b  = blockIdx.z, h = blockIdx.y;
    const int n0 = blockIdx.x * 128;
    const int bh = b * HH + h;
    const int t  = threadIdx.x;
    const int wid = t >> 5, lane = t & 31;
    const int g = lane >> 2, tg = lane & 3;
    const int wr = wid * 32;
    const int lrow = lane & 7;
    const int lcol = (lane >> 3) * 8;

    const __half* Kg = k + (size_t)bh * M * 64;
    const __half* Vg = v + (size_t)bh * 64 * M;
    const int nT = M / 64;

    auto loadKV = [&](int tile, int buf) {
        uint32_t kd = smem_u32(Ks + (size_t)buf * 64 * LDB);
        uint32_t vd = smem_u32(Vs + (size_t)buf * VROWS * LDB);
        const __half* Kn = Kg + (size_t)tile * 64 * 64;
        const __half* Vn = Vg + (size_t)tile * 64;
        #pragma unroll
        for (int i = 0; i < 4; i++) {
            int idx = t + i * 128;
            int r = idx >> 3, c = (idx & 7) * 8;
            cp16(kd + (uint32_t)(r * LDB + c) * 2, Kn + r * 64 + c);
            cp16(vd + (uint32_t)(r * LDB + c) * 2, Vn + (size_t)r * M + c);
        }
        CP_COMMIT();
    };

    // prologue: tiles 0 and 1 (nT >= 2 always here)
    loadKV(0, 0);
    loadKV(1, 1);

    // ones/zeros rows 64..71 of all 3 V buffers
    {
        const __half one = __float2half(1.0f);
        const __half zer = __float2half(0.0f);
        for (int i = t; i < 3 * 8 * LDB; i += 128) {
            int buf = i / (8 * LDB);
            int rem = i - buf * 8 * LDB;
            int r = rem / LDB, c = rem - r * LDB;
            Vs[(size_t)buf * VROWS * LDB + (64 + r) * LDB + c] = (r == 0) ? one : zer;
        }
    }

    // stage Q
    {
        const __half* Qg = q + ((size_t)bh * N + n0) * 64;
        #pragma unroll
        for (int i = 0; i < 8; i++) {
            int idx = t + i * 128;
            int r = idx >> 3, c = (idx & 7) * 8;
            *reinterpret_cast<uint4*>(Qs + r * LDB + c) =
                *reinterpret_cast<const uint4*>(Qg + r * 64 + c);
        }
    }
    __syncthreads();

    uint32_t Qf[2][4][4];
    #pragma unroll
    for (int mt = 0; mt < 2; mt++) {
        int r0 = wr + mt * 16 + g;
        #pragma unroll
        for (int kk = 0; kk < 4; kk++) {
            Qf[mt][kk][0] = *reinterpret_cast<uint32_t*>(Qs + (r0    ) * LDB + kk * 16 + 2 * tg);
            Qf[mt][kk][1] = *reinterpret_cast<uint32_t*>(Qs + (r0 + 8) * LDB + kk * 16 + 2 * tg);
            Qf[mt][kk][2] = *reinterpret_cast<uint32_t*>(Qs + (r0    ) * LDB + kk * 16 + 2 * tg + 8);
            Qf[mt][kk][3] = *reinterpret_cast<uint32_t*>(Qs + (r0 + 8) * LDB + kk * 16 + 2 * tg + 8);
        }
    }

    float Of[9][2][4] = {};

    int cb = 0;    // current buffer = tt % 3
    int sb = 2;    // stage buffer   = (tt+2) % 3
    for (int tt = 0; tt < nT; tt++) {
        if (tt + 1 < nT) { CP_WAIT(1); } else { CP_WAIT(0); }
        __syncthreads();
        if (tt + 2 < nT) loadKV(tt + 2, sb);

        const uint32_t kb = smem_u32(Ks + (size_t)cb * 64 * LDB);
        const uint32_t vb = smem_u32(Vs + (size_t)cb * VROWS * LDB);

        float Sc[8][2][4] = {};
        #pragma unroll
        for (int jp = 0; jp < 4; jp++) {
            uint32_t Kf[2][8];
            #pragma unroll
            for (int jj = 0; jj < 2; jj++) {
                uint32_t a = kb + (uint32_t)(((jp * 2 + jj) * 8 + lrow) * LDB + lcol) * 2;
                ldsm4(Kf[jj],     a);
                ldsm4(Kf[jj] + 4, a + 64);
            }
            #pragma unroll
            for (int kk = 0; kk < 4; kk++) {
                mma16f(Sc[jp * 2    ][0], Qf[0][kk], Kf[0][kk * 2], Kf[0][kk * 2 + 1]);
                mma16f(Sc[jp * 2    ][1], Qf[1][kk], Kf[0][kk * 2], Kf[0][kk * 2 + 1]);
                mma16f(Sc[jp * 2 + 1][0], Qf[0][kk], Kf[1][kk * 2], Kf[1][kk * 2 + 1]);
                mma16f(Sc[jp * 2 + 1][1], Qf[1][kk], Kf[1][kk * 2], Kf[1][kk * 2 + 1]);
            }
        }

        uint32_t Pa[4][2][4];
        #pragma unroll
        for (int mt = 0; mt < 2; mt++) {
            #pragma unroll
            for (int j = 0; j < 8; j++) {
                int kk = j >> 1, hf = (j & 1) * 2;
                Pa[kk][mt][hf    ] = ex2h2(packh(Sc[j][mt][0], Sc[j][mt][1]));
                Pa[kk][mt][hf + 1] = ex2h2(packh(Sc[j][mt][2], Sc[j][mt][3]));
            }
        }

        #pragma unroll
        for (int jp = 0; jp < 4; jp++) {
            uint32_t Vf[2][8];
            #pragma unroll
            for (int jj = 0; jj < 2; jj++) {
                uint32_t a = vb + (uint32_t)(((jp * 2 + jj) * 8 + lrow) * LDB + lcol) * 2;
                ldsm4(Vf[jj],     a);
                ldsm4(Vf[jj] + 4, a + 64);
            }
            #pragma unroll
            for (int kk = 0; kk < 4; kk++) {
                mma16f(Of[jp * 2    ][0], Pa[kk][0], Vf[0][kk * 2], Vf[0][kk * 2 + 1]);
                mma16f(Of[jp * 2    ][1], Pa[kk][1], Vf[0][kk * 2], Vf[0][kk * 2 + 1]);
                mma16f(Of[jp * 2 + 1][0], Pa[kk][0], Vf[1][kk * 2], Vf[1][kk * 2 + 1]);
                mma16f(Of[jp * 2 + 1][1], Pa[kk][1], Vf[1][kk * 2], Vf[1][kk * 2 + 1]);
            }
        }
        {
            uint32_t Vf8[8];
            uint32_t a = vb + (uint32_t)((64 + lrow) * LDB + lcol) * 2;
            ldsm4(Vf8,     a);
            ldsm4(Vf8 + 4, a + 64);
            #pragma unroll
            for (int kk = 0; kk < 4; kk++) {
                mma16f(Of[8][0], Pa[kk][0], Vf8[kk * 2], Vf8[kk * 2 + 1]);
                mma16f(Of[8][1], Pa[kk][1], Vf8[kk * 2], Vf8[kk * 2 + 1]);
            }
        }

        cb = (cb == 2) ? 0 : cb + 1;
        sb = (sb == 2) ? 0 : sb + 1;
    }

    float linv[2][2];
    #pragma unroll
    for (int mt = 0; mt < 2; mt++) {
        float l0 = __shfl_sync(0xffffffffu, Of[8][mt][0], lane & ~3);
        float l1 = __shfl_sync(0xffffffffu, Of[8][mt][2], lane & ~3);
        linv[mt][0] = 1.0f / l0;
        linv[mt][1] = 1.0f / l1;
    }

    __syncthreads();   // all warps done with K/V smem; reuse as OTh
    #pragma unroll
    for (int j = 0; j < 8; j++) {
        #pragma unroll
        for (int mt = 0; mt < 2; mt++) {
            int r0 = wr + mt * 16 + g;
            *reinterpret_cast<uint32_t*>(OTh + (r0    ) * 72 + j * 8 + 2 * tg) =
                packh(Of[j][mt][0] * linv[mt][0], Of[j][mt][1] * linv[mt][0]);
            *reinterpret_cast<uint32_t*>(OTh + (r0 + 8) * 72 + j * 8 + 2 * tg) =
                packh(Of[j][mt][2] * linv[mt][1], Of[j][mt][3] * linv[mt][1]);
        }
    }
    __syncthreads();

    __half* Ag = attn + ((size_t)b * N + n0) * DD + h * 64;
    #pragma unroll
    for (int it = 0; it < 8; it++) {
        int n = it * 16 + (t >> 3);
        int qd = (t & 7) * 8;
        uint4 val = *reinterpret_cast<const uint4*>(OTh + n * 72 + qd);
        *reinterpret_cast<uint4*>(Ag + (size_t)n * DD + qd) = val;
    }
}

// ---------------------------------------------------------------------------
// fp16 GEMM body, BK=64, 3-stage cp.async, one sync per k-iter, ldmatrix.
// Tile 128x128; 8 warps = 2(o) x 4(n), warp tile 64x32.
// smem: Ws[3][128][72] + Xs[3][128][72] = 110592 B.
// ---------------------------------------------------------------------------
#define LDH2 72

struct GemmOut {
    float acc[4][4][4];
    int o0, n0, wo, wn, g, tg;
};

__device__ __forceinline__ void gemm_body_h(
    const __half* __restrict__ W, const __half* __restrict__ X0, int S0, int C0,
    const __half* __restrict__ X1, int S1, int b, int IC, int N,
    int o0, int n0, __half* sm, GemmOut& R)
{
    __half* Ws = sm;                    // [3][128][LDH2]
    __half* Xs = sm + 3 * 128 * LDH2;   // [3][128][LDH2]

    const int t  = threadIdx.x;
    const int wid = t >> 5, lane = t & 31;
    R.g = lane >> 2; R.tg = lane & 3;
    R.wo = (wid & 1) * 64;
    R.wn = (wid >> 1) * 32;
    R.o0 = o0; R.n0 = n0;
    const int a_row = (lane & 7) + ((lane >> 3) & 1) * 8;
    const int a_col = (lane >> 4) * 8;
    const int b_row = lane & 7;
    const int b_col = (lane >> 3) * 8;

    auto stage = [&](int buf, int k0) {
        uint32_t wd = smem_u32(Ws + buf * 128 * LDH2);
        uint32_t xd = smem_u32(Xs + buf * 128 * LDH2);
        #pragma unroll
        for (int i = 0; i < 4; i++) {
            int idx = t + i * 256;
            int r = idx >> 3, c = (idx & 7) * 8;
            cp16(wd + (uint32_t)(r * LDH2 + c) * 2, W + (size_t)(o0 + r) * IC + k0 + c);
        }
        const __half* xb; int S;
        if (k0 < C0) { xb = X0 + (size_t)b * N * S0 + k0;        S = S0; }
        else         { xb = X1 + (size_t)b * N * S1 + (k0 - C0); S = S1; }
        #pragma unroll
        for (int i = 0; i < 4; i++) {
            int idx = t + i * 256;
            int r = idx >> 3, c = (idx & 7) * 8;
            cp16(xd + (uint32_t)(r * LDH2 + c) * 2, xb + (size_t)(n0 + r) * S + c);
        }
        CP_COMMIT();
    };

    const int nK = IC / 64;
    stage(0, 0);
    if (nK > 1) stage(1, 64);

    #pragma unroll
    for (int a = 0; a < 4; a++)
        #pragma unroll
        for (int c = 0; c < 4; c++)
            #pragma unroll
            for (int d = 0; d < 4; d++) R.acc[a][c][d] = 0.f;

    int cbuf = 0, sbuf = 2;
    for (int kt = 0; kt < nK; kt++) {
        if (kt + 1 < nK) { CP_WAIT(1); } else { CP_WAIT(0); }
        __syncthreads();
        if (kt + 2 < nK) stage(sbuf, (kt + 2) * 64);

        const uint32_t wb = smem_u32(Ws + cbuf * 128 * LDH2);
        const uint32_t xb = smem_u32(Xs + cbuf * 128 * LDH2);

        #pragma unroll
        for (int h2 = 0; h2 < 2; h2++) {
            uint32_t Bf[4][4];
            #pragma unroll
            for (int nt = 0; nt < 4; nt++)
                ldsm4(Bf[nt], xb + (uint32_t)((R.wn + nt * 8 + b_row) * LDH2
                                              + h2 * 32 + b_col) * 2);
            #pragma unroll
            for (int ks = 0; ks < 2; ks++) {
                uint32_t Af[4][4];
                #pragma unroll
                for (int mt = 0; mt < 4; mt++)
                    ldsm4(Af[mt], wb + (uint32_t)((R.wo + mt * 16 + a_row) * LDH2
                                                  + h2 * 32 + ks * 16 + a_col) * 2);
                #pragma unroll
                for (int nt = 0; nt < 4; nt++)
                    #pragma unroll
                    for (int mt = 0; mt < 4; mt++)
                        mma16f(R.acc[mt][nt], Af[mt], Bf[nt][ks * 2], Bf[nt][ks * 2 + 1]);
            }
        }
        cbuf = (cbuf == 2) ? 0 : cbuf + 1;
        sbuf = (sbuf == 2) ? 0 : sbuf + 1;
    }
    __syncthreads();   // protect smem reuse by epilogues
}

// generic projection. mode 0: fp32 (B,OC,N); mode 1: fp16 (B,OC,N).
__global__ void __launch_bounds__(256, 2)
gemm_h(const __half* __restrict__ W, const float* __restrict__ bias,
       const __half* __restrict__ X0, int S0, int C0,
       const __half* __restrict__ X1, int S1,
       void* __restrict__ out, int OC, int IC, int N, int mode)
{
    extern __shared__ __half smh[];
    GemmOut R;
    gemm_body_h(W, X0, S0, C0, X1, S1, blockIdx.z, IC, N,
                blockIdx.y * 128, blockIdx.x * 128, smh, R);

    #pragma unroll
    for (int mt = 0; mt < 4; mt++) {
        int o_g  = R.o0 + R.wo + mt * 16 + R.g;
        int o_g8 = o_g + 8;
        float bg  = bias[o_g];
        float bg8 = bias[o_g8];
        #pragma unroll
        for (int nt = 0; nt < 4; nt++) {
            int n = R.n0 + R.wn + nt * 8 + 2 * R.tg;
            float c0 = R.acc[mt][nt][0] + bg,  c1 = R.acc[mt][nt][1] + bg;
            float c2 = R.acc[mt][nt][2] + bg8, c3 = R.acc[mt][nt][3] + bg8;
            if (mode == 0) {
                float* o32 = (float*)out;
                *reinterpret_cast<float2*>(o32 + ((size_t)blockIdx.z * OC + o_g ) * N + n) =
                    make_float2(c0, c1);
                *reinterpret_cast<float2*>(o32 + ((size_t)blockIdx.z * OC + o_g8) * N + n) =
                    make_float2(c2, c3);
            } else {
                __half* o16 = (__half*)out;
                *reinterpret_cast<uint32_t*>(o16 + ((size_t)blockIdx.z * OC + o_g ) * N + n) =
                    packh(c0, c1);
                *reinterpret_cast<uint32_t*>(o16 + ((size_t)blockIdx.z * OC + o_g8) * N + n) =
                    packh(c2, c3);
            }
        }
    }
}

// fused Q/K/V projection with smem-staged coalesced epilogue for q/k.
__global__ void __launch_bounds__(256, 2)
gemm_qkv(const __half* __restrict__ wts,
         const float* __restrict__ bq, const float* __restrict__ bk,
         const float* __restrict__ bv,
         const __half* __restrict__ xt, const __half* __restrict__ st,
         __half* __restrict__ qp, __half* __restrict__ kp,
         __half* __restrict__ vp, int N)
{
    extern __shared__ __half smh[];
    const int z = blockIdx.z;
    const int which = z >> 1;
    const int b = z & 1;
    const __half* W    = wts + which * 65536;
    const float* bias  = (which == 0) ? bq : (which == 1) ? bk : bv;
    const __half* X    = (which == 0) ? xt : st;
    const float oscale = (which == 0) ? QSCALE : 1.0f;

    GemmOut R;
    gemm_body_h(W, X, DD, DD, nullptr, DD, b, DD, N,
                blockIdx.y * 128, blockIdx.x * 128, smh, R);

    const int t = threadIdx.x;

    if (which < 2) {
        __half* St = smh;
        #pragma unroll
        for (int mt = 0; mt < 4; mt++) {
            int ol  = R.wo + mt * 16 + R.g;
            int ol8 = ol + 8;
            float bg  = bias[R.o0 + ol];
            float bg8 = bias[R.o0 + ol8];
            int col  = (ol  & 3) * 32 + (ol  >> 2);
            int col8 = (ol8 & 3) * 32 + (ol8 >> 2);
            #pragma unroll
            for (int nt = 0; nt < 4; nt++) {
                int nl = R.wn + nt * 8 + 2 * R.tg;
                St[(nl    ) * 136 + col ] = __float2half_rn((R.acc[mt][nt][0] + bg)  * oscale);
                St[(nl + 1) * 136 + col ] = __float2half_rn((R.acc[mt][nt][1] + bg)  * oscale);
                St[(nl    ) * 136 + col8] = __float2half_rn((R.acc[mt][nt][2] + bg8) * oscale);
                St[(nl + 1) * 136 + col8] = __float2half_rn((R.acc[mt][nt][3] + bg8) * oscale);
            }
        }
        __syncthreads();

        __half* out = (which == 0) ? qp : kp;
        const int di0 = R.o0 >> 2;
        #pragma unroll
        for (int it = 0; it < 8; it++) {
            int idx = t + it * 256;
            int quad = idx & 3, pr = idx >> 2;
            int hh = pr >> 7, nl = pr & 127;
            uint4 val = *reinterpret_cast<const uint4*>(St + nl * 136 + hh * 32 + quad * 8);
            *reinterpret_cast<uint4*>(
                out + (((size_t)b * HH + hh) * N + R.n0 + nl) * 64 + di0 + quad * 8) = val;
        }
    } else {
        #pragma unroll
        for (int mt = 0; mt < 4; mt++) {
            int o_g  = R.o0 + R.wo + mt * 16 + R.g;
            int o_g8 = o_g + 8;
            float bg  = bias[o_g];
            float bg8 = bias[o_g8];
            #pragma unroll
            for (int nt = 0; nt < 4; nt++) {
                int n = R.n0 + R.wn + nt * 8 + 2 * R.tg;
                int h0 = o_g & 3,  d0 = o_g >> 2;
                int h1 = o_g8 & 3, d1 = o_g8 >> 2;
                *reinterpret_cast<uint32_t*>(
                    vp + (((size_t)b * HH + h0) * 64 + d0) * N + n) =
                    packh(R.acc[mt][nt][0] + bg, R.acc[mt][nt][1] + bg);
                *reinterpret_cast<uint32_t*>(
                    vp + (((size_t)b * HH + h1) * 64 + d1) * N + n) =
                    packh(R.acc[mt][nt][2] + bg8, R.acc[mt][nt][3] + bg8);
            }
        }
    }
}

// ---------------------------------------------------------------------------
// InstanceNorm stats + normalize/transpose
// ---------------------------------------------------------------------------
__global__ void inst_stats(const __half* __restrict__ hb, float* __restrict__ stats, int N)
{
    int row = blockIdx.x;
    const __half* p = hb + (size_t)row * N;

    float s = 0.f, s2 = 0.f;
    for (int i = threadIdx.x * 8; i < N; i += 256 * 8) {
        uint4 raw = *reinterpret_cast<const uint4*>(p + i);
        const __half2* h2 = reinterpret_cast<const __half2*>(&raw);
        #pragma unroll
        for (int kk = 0; kk < 4; kk++) {
            float2 f = __half22float2(h2[kk]);
            s  += f.x + f.y;
            s2 += f.x * f.x + f.y * f.y;
        }
    }
    #pragma unroll
    for (int off = 16; off > 0; off >>= 1) {
        s  += __shfl_xor_sync(0xffffffffu, s,  off);
        s2 += __shfl_xor_sync(0xffffffffu, s2, off);
    }
    __shared__ float sh[16];
    int wid = threadIdx.x >> 5, lid = threadIdx.x & 31;
    if (lid == 0) { sh[wid] = s; sh[wid + 8] = s2; }
    __syncthreads();
    if (threadIdx.x == 0) {
        s = 0.f; s2 = 0.f;
        #pragma unroll
        for (int w = 0; w < 8; w++) { s += sh[w]; s2 += sh[w + 8]; }
        float mean = s / (float)N;
        float var  = s2 / (float)N - mean * mean;
        stats[row * 2]     = mean;
        stats[row * 2 + 1] = rsqrtf(var + 1e-5f);
    }
}

__global__ void norm_transpose(const __half* __restrict__ hb, const float* __restrict__ stats,
                               __half* __restrict__ ht, int N)
{
    __shared__ __half tile[32][33];
    const int b = blockIdx.z;
    const int c0 = blockIdx.y * 32, n0 = blockIdx.x * 32;
    const int tx = threadIdx.x & 31, ty = threadIdx.x >> 5;

    #pragma unroll
    for (int i = 0; i < 4; i++) {
        int c = ty + i * 8;
        int row = b * 512 + c0 + c;
        float mu  = stats[row * 2];
        float inv = stats[row * 2 + 1];
        float v = __half2float(hb[(size_t)row * N + n0 + tx]);
        tile[c][tx] = __float2half_rn(fmaxf(0.f, (v - mu) * inv));
    }
    __syncthreads();
    #pragma unroll
    for (int i = 0; i < 4; i++) {
        int n = ty + i * 8;
        ht[((size_t)b * N + n0 + n) * 512 + c0 + tx] = tile[tx][n];
    }
}

// ---------------------------------------------------------------------------
extern "C" void kernel_launch(void* const* d_in, const int* in_sizes, int n_in,
                              void* d_out, int out_size)
{
    const float* x   = (const float*)d_in[0];
    const float* src = (const float*)d_in[1];
    const float* Wq  = (const float*)d_in[2];
    const float* bq  = (const float*)d_in[3];
    const float* Wk  = (const float*)d_in[4];
    const float* bk  = (const float*)d_in[5];
    const float* Wv  = (const float*)d_in[6];
    const float* bv  = (const float*)d_in[7];
    const float* Wm  = (const float*)d_in[8];
    const float* bm  = (const float*)d_in[9];
    const float* W1  = (const float*)d_in[10];
    const float* b1  = (const float*)d_in[11];
    const float* W2  = (const float*)d_in[12];
    const float* b2  = (const float*)d_in[13];

    const int B = BB, D = DD;
    const int N = in_sizes[0] / (B * D);
    const int M = in_sizes[1] / (B * D);

    __half *qp, *kp, *vp, *xtp, *stp, *attnp, *hp, *htp, *wts, *wcat;
    float *bf, *stats;
    cudaGetSymbolAddress((void**)&qp,    g_q);
    cudaGetSymbolAddress((void**)&kp,    g_k);
    cudaGetSymbolAddress((void**)&vp,    g_v);
    cudaGetSymbolAddress((void**)&xtp,   g_xt);
    cudaGetSymbolAddress((void**)&stp,   g_st);
    cudaGetSymbolAddress((void**)&attnp, g_attn);
    cudaGetSymbolAddress((void**)&hp,    g_h);
    cudaGetSymbolAddress((void**)&htp,   g_ht);
    cudaGetSymbolAddress((void**)&wts,   g_wts);
    cudaGetSymbolAddress((void**)&wcat,  g_wcat);
    cudaGetSymbolAddress((void**)&bf,    g_bf);
    cudaGetSymbolAddress((void**)&stats, g_stats);

    const int gsmem = 6 * 128 * LDH2 * (int)sizeof(__half);  // 110592
    const int fsmem = 27648 + 31104 + 18432;                  // 77184
    cudaFuncSetAttribute(gemm_h,   cudaFuncAttributeMaxDynamicSharedMemorySize, gsmem);
    cudaFuncSetAttribute(gemm_qkv, cudaFuncAttributeMaxDynamicSharedMemorySize, gsmem);
    cudaFuncSetAttribute(flash_attn_fp16, cudaFuncAttributeMaxDynamicSharedMemorySize, fsmem);

    // 0. fused producers (weights fp16 + input transpose + W1 fold)
    const int nProd = 2560 + (N / 32) * 8 * 4 + 512;
    producers<<<nProd, 256>>>(Wq, Wk, Wv, Wm, W1, W2, wts,
                              x, src, xtp, stp, b1, bm, wcat, bf, N);

    // 1. fused Q/K/V projections
    gemm_qkv<<<dim3(N / 128, D / 128, 3 * B), 256, gsmem>>>(
        wts, bq, bk, bv, xtp, stp, qp, kp, vp, N);

    // 2. fp16 flash attention -> attn_t (B,N,256)
    flash_attn_fp16<<<dim3(N / 128, HH, B), 128, fsmem>>>(qp, kp, vp, attnp, N, M);

    // 3. fused W1 layer -> h (B,2D,N) fp16
    gemm_h<<<dim3(N / 128, (2 * D) / 128, B), 256, gsmem>>>(
        wcat, bf, xtp, D, D, attnp, D, hp, 2 * D, 2 * D, N, 1);

    // 4. InstanceNorm stats + normalize/transpose -> ht (B,N,512)
    inst_stats<<<B * 2 * D, 256>>>(hp, stats, N);
    norm_transpose<<<dim3(N / 32, (2 * D) / 32, B), 256>>>(hp, stats, htp, N);

    // 5. final projection -> d_out (B,D,N) fp32
    gemm_h<<<dim3(N / 128, D / 128, B), 256, gsmem>>>(
        wts + OFF_W2, b2, htp, 2 * D, 2 * D, nullptr, 2 * D, d_out, D, 2 * D, N, 0);
}